// round 9
// baseline (speedup 1.0000x reference)
#include <cuda_runtime.h>
#include <cstdint>

#define PI_F 3.14159265358979323846f
typedef unsigned long long u64;

// ---------------- scratch (device globals; no runtime allocation) ----------------
__device__ float2 g_spec[256u * 256u * 129u];      // [img=b*32+ch][row][k] spectrum
__device__ float  g_x1[8u * 256u * 256u * 32u];    // [pix][32] local-mixer out
__device__ float  g_x2[256u * 256u * 256u];        // [img][row][w] global-mixer out
__device__ float  g_posT[4 * 64 * 64];             // pos transposed: [h][j][i]

// ---------------- helpers ----------------
__device__ __forceinline__ u64 fma2(u64 a, u64 b, u64 c) {
    u64 d; asm("fma.rn.f32x2 %0, %1, %2, %3;" : "=l"(d) : "l"(a), "l"(b), "l"(c)); return d;
}
__device__ __forceinline__ u64 pack2(float lo, float hi) {
    u64 r; asm("mov.b64 %0, {%1, %2};" : "=l"(r) : "f"(lo), "f"(hi)); return r;
}
__device__ __forceinline__ float2 unpk(u64 v) {
    float2 r; asm("mov.b64 {%0, %1}, %2;" : "=f"(r.x), "=f"(r.y) : "l"(v)); return r;
}
__device__ __forceinline__ float2 cmulf(float2 a, float2 b) {
    return make_float2(a.x * b.x - a.y * b.y, a.x * b.y + a.y * b.x);
}
__device__ __forceinline__ float2 cadd(float2 a, float2 b) { return make_float2(a.x + b.x, a.y + b.y); }
__device__ __forceinline__ float2 csub(float2 a, float2 b) { return make_float2(a.x - b.x, a.y - b.y); }
__device__ __forceinline__ int rev5(int l) {
    return ((l & 1) << 4) | ((l & 2) << 2) | (l & 4) | ((l & 8) >> 2) | ((l & 16) >> 4);
}
// smem index maps (conflict-free by construction)
__device__ __forceinline__ int zin(int n, int f) { return n ^ (4 * f); }            // natural-order staging
__device__ __forceinline__ int zq(int q, int p)  { return q * 32 + (p ^ (4 * q)); } // spectral (q,p) layout
__device__ __forceinline__ int zpos(int k)       { return zq(k & 7, k >> 3); }      // spectral by k

// ---------------- warp-level 256-pt FFT: 8 values/lane, 1 warp per FFT ----------
// forward: natural (lane l, reg m holds x[l+32m]) -> spectral: (reg r, lane l)
// holds X[k], k = Q[r] + 8*rev5(l), Q = {0,4,2,6,1,5,3,7}.
// inverse: exact structural reverse (spectral layout in -> natural out, unscaled).

template <int SIGN>
__device__ __forceinline__ void reg_fft8_dif(float2 v[8]) {
    const float S = (float)SIGN;
    const float C = 0.70710678118654752f;
    {   // h=4, twiddle W8^{S*m}
        float2 t0 = csub(v[0], v[4]), t1 = csub(v[1], v[5]);
        float2 t2 = csub(v[2], v[6]), t3 = csub(v[3], v[7]);
        v[0] = cadd(v[0], v[4]); v[1] = cadd(v[1], v[5]);
        v[2] = cadd(v[2], v[6]); v[3] = cadd(v[3], v[7]);
        v[4] = t0;
        v[5] = make_float2(C * (t1.x - S * t1.y), C * (S * t1.x + t1.y));
        v[6] = make_float2(-S * t2.y, S * t2.x);
        v[7] = make_float2(-C * (t3.x + S * t3.y), C * (S * t3.x - t3.y));
    }
    #pragma unroll
    for (int b = 0; b < 8; b += 4) {   // h=2, twiddle W4^{S*m}
        float2 t0 = csub(v[b], v[b + 2]), t1 = csub(v[b + 1], v[b + 3]);
        v[b] = cadd(v[b], v[b + 2]); v[b + 1] = cadd(v[b + 1], v[b + 3]);
        v[b + 2] = t0;
        v[b + 3] = make_float2(-S * t1.y, S * t1.x);
    }
    #pragma unroll
    for (int b = 0; b < 8; b += 2) {   // h=1
        float2 a = v[b], c = v[b + 1];
        v[b] = cadd(a, c); v[b + 1] = csub(a, c);
    }
}

template <int SIGN>
__device__ __forceinline__ void reg_fft8_dit(float2 v[8]) {
    const float S = (float)SIGN;
    const float C = 0.70710678118654752f;
    #pragma unroll
    for (int b = 0; b < 8; b += 2) {   // d=1
        float2 a = v[b], c = v[b + 1];
        v[b] = cadd(a, c); v[b + 1] = csub(a, c);
    }
    #pragma unroll
    for (int b = 0; b < 8; b += 4) {   // d=2, twiddle W4^{S*j}
        float2 t0 = v[b + 2];
        float2 t1 = make_float2(-S * v[b + 3].y, S * v[b + 3].x);
        float2 a0 = v[b], a1 = v[b + 1];
        v[b] = cadd(a0, t0); v[b + 2] = csub(a0, t0);
        v[b + 1] = cadd(a1, t1); v[b + 3] = csub(a1, t1);
    }
    {   // d=4, twiddle W8^{S*j}
        float2 t0 = v[4];
        float2 t1 = make_float2(C * (v[5].x - S * v[5].y), C * (S * v[5].x + v[5].y));
        float2 t2 = make_float2(-S * v[6].y, S * v[6].x);
        float2 t3 = make_float2(-C * (v[7].x + S * v[7].y), C * (S * v[7].x - v[7].y));
        float2 a0 = v[0], a1 = v[1], a2 = v[2], a3 = v[3];
        v[0] = cadd(a0, t0); v[4] = csub(a0, t0);
        v[1] = cadd(a1, t1); v[5] = csub(a1, t1);
        v[2] = cadd(a2, t2); v[6] = csub(a2, t2);
        v[3] = cadd(a3, t3); v[7] = csub(a3, t3);
    }
}

template <int SIGN>
__device__ __forceinline__ void mid_twiddle(float2 v[8], int lane) {
    // v[r] *= W256^{SIGN * lane * Q[r]}, Q = {0,4,2,6,1,5,3,7}
    float ang = (float)SIGN * (2.0f * PI_F / 256.0f) * (float)lane;
    float sn, cs; __sincosf(ang, &sn, &cs);
    float2 w1 = make_float2(cs, sn);
    float2 w2 = cmulf(w1, w1);
    float2 w3 = cmulf(w2, w1);
    float2 w4 = cmulf(w2, w2);
    float2 w5 = cmulf(w4, w1);
    float2 w6 = cmulf(w4, w2);
    float2 w7 = cmulf(w4, w3);
    v[1] = cmulf(v[1], w4);
    v[2] = cmulf(v[2], w2);
    v[3] = cmulf(v[3], w6);
    v[4] = cmulf(v[4], w1);
    v[5] = cmulf(v[5], w5);
    v[6] = cmulf(v[6], w3);
    v[7] = cmulf(v[7], w7);
}

template <int SIGN>
__device__ __forceinline__ void lane_fft_dif(float2 v[8], int lane) {
    #pragma unroll
    for (int h = 16; h >= 1; h >>= 1) {
        int j = lane & (h - 1);
        float ang = (float)SIGN * (2.0f * PI_F / 32.0f) * (float)(j * (16 / h));
        float sn, cs; __sincosf(ang, &sn, &cs);
        bool upper = (lane & h) != 0;
        #pragma unroll
        for (int r = 0; r < 8; r++) {
            float ox = __shfl_xor_sync(0xffffffffu, v[r].x, h);
            float oy = __shfl_xor_sync(0xffffffffu, v[r].y, h);
            if (!upper) {
                v[r] = make_float2(v[r].x + ox, v[r].y + oy);
            } else {
                float tx = ox - v[r].x, ty = oy - v[r].y;
                v[r] = make_float2(tx * cs - ty * sn, tx * sn + ty * cs);
            }
        }
    }
}

template <int SIGN>
__device__ __forceinline__ void lane_fft_dit(float2 v[8], int lane) {
    #pragma unroll
    for (int d = 1; d <= 16; d <<= 1) {
        int j = lane & (d - 1);
        float ang = (float)SIGN * (2.0f * PI_F / 32.0f) * (float)(j * (16 / d));
        float sn, cs; __sincosf(ang, &sn, &cs);
        bool upper = (lane & d) != 0;
        #pragma unroll
        for (int r = 0; r < 8; r++) {
            float ox = __shfl_xor_sync(0xffffffffu, v[r].x, d);
            float oy = __shfl_xor_sync(0xffffffffu, v[r].y, d);
            if (!upper) {
                float tx = ox * cs - oy * sn, ty = ox * sn + oy * cs;
                v[r] = make_float2(v[r].x + tx, v[r].y + ty);
            } else {
                float tx = v[r].x * cs - v[r].y * sn, ty = v[r].x * sn + v[r].y * cs;
                v[r] = make_float2(ox - tx, oy - ty);
            }
        }
    }
}

__device__ __forceinline__ void warp_fft256_fwd(float2 v[8], int lane) {
    reg_fft8_dif<-1>(v);
    mid_twiddle<-1>(v, lane);
    lane_fft_dif<-1>(v, lane);
}
__device__ __forceinline__ void warp_fft256_inv(float2 v[8], int lane) {
    lane_fft_dit<1>(v, lane);
    mid_twiddle<1>(v, lane);
    reg_fft8_dit<1>(v);
}

// ---------------- pos transpose (tiny, once per launch) ----------------
__global__ __launch_bounds__(256) void transpose_pos_kernel(const float* __restrict__ pos)
{
    int idx = blockIdx.x * 256 + threadIdx.x;
    int h = idx >> 12;
    int j = (idx >> 6) & 63;
    int i = idx & 63;
    g_posT[idx] = pos[((h * 64) + i) * 64 + j];
}

// ---------------- local mixer: window attention (unchanged, working) ----------------
__global__ __launch_bounds__(256) void attn_kernel(
    const float* __restrict__ x, const float* __restrict__ wqkv,
    const float* __restrict__ bqkv)
{
    __shared__ float xw[64][36];
    __shared__ float wq[96][36];
    __shared__ float bq[96];
    __shared__ float ks[64][36];
    __shared__ float vs[64][36];

    int t = threadIdx.x;
    int wid = blockIdx.x;
    int b   = wid >> 10;
    int hb  = (wid >> 5) & 31;
    int wb  = wid & 31;

    {
        const float4* xv = (const float4*)x;
        #pragma unroll
        for (int e = 0; e < 2; e++) {
            int l = t + e * 256;
            int n = l >> 3;
            int q4 = l & 7;
            int i = n >> 3, j = n & 7;
            size_t pix = ((size_t)(b * 256 + hb * 8 + i) * 256) + (wb * 8 + j);
            *(float4*)&xw[n][q4 * 4] = xv[pix * 16 + q4];
        }
        #pragma unroll
        for (int e = 0; e < 12; e++) {
            int l = t + e * 256;
            wq[l >> 5][l & 31] = wqkv[l];
        }
        if (t < 96) bq[t] = bqkv[t];
    }
    __syncthreads();

    int i  = t & 63;
    int hq = t >> 6;

    u64 xr[16];
    #pragma unroll
    for (int c = 0; c < 8; c++) {
        ulonglong2 v = *(const ulonglong2*)&xw[i][4 * c];
        xr[2 * c] = v.x; xr[2 * c + 1] = v.y;
    }

    u64 q2[4];
    #pragma unroll
    for (int kind = 0; kind < 3; kind++) {
        float o[8];
        #pragma unroll
        for (int dd = 0; dd < 8; dd++) {
            int d = kind * 32 + hq * 8 + dd;
            const float* wrow = &wq[d][0];
            u64 a0 = 0ull, a1 = 0ull;
            #pragma unroll
            for (int c = 0; c < 4; c++) {
                ulonglong2 w0 = *(const ulonglong2*)(wrow + 8 * c);
                ulonglong2 w1 = *(const ulonglong2*)(wrow + 8 * c + 4);
                a0 = fma2(xr[4 * c],     w0.x, a0);
                a1 = fma2(xr[4 * c + 1], w0.y, a1);
                a0 = fma2(xr[4 * c + 2], w1.x, a0);
                a1 = fma2(xr[4 * c + 3], w1.y, a1);
            }
            float2 p = unpk(a0), q = unpk(a1);
            o[dd] = p.x + p.y + q.x + q.y + bq[d];
        }
        if (kind == 0) {
            #pragma unroll
            for (int c = 0; c < 4; c++)
                q2[c] = pack2(o[2 * c]     * 0.35355339059327373f,
                              o[2 * c + 1] * 0.35355339059327373f);
        } else if (kind == 1) {
            *(float4*)&ks[i][hq * 8]     = make_float4(o[0], o[1], o[2], o[3]);
            *(float4*)&ks[i][hq * 8 + 4] = make_float4(o[4], o[5], o[6], o[7]);
        } else {
            *(float4*)&vs[i][hq * 8]     = make_float4(o[0], o[1], o[2], o[3]);
            *(float4*)&vs[i][hq * 8 + 4] = make_float4(o[4], o[5], o[6], o[7]);
        }
    }
    __syncthreads();

    {
        const float* pT = g_posT + hq * 4096 + i;
        float sim[64];
        float m = -1e30f;
        #pragma unroll
        for (int j = 0; j < 64; j++) {
            ulonglong2 k0 = *(const ulonglong2*)&ks[j][hq * 8];
            ulonglong2 k1 = *(const ulonglong2*)&ks[j][hq * 8 + 4];
            u64 a = 0ull;
            a = fma2(q2[0], k0.x, a);
            a = fma2(q2[1], k0.y, a);
            a = fma2(q2[2], k1.x, a);
            a = fma2(q2[3], k1.y, a);
            float2 p = unpk(a);
            float s = p.x + p.y + pT[j * 64];
            sim[j] = s;
            m = fmaxf(m, s);
        }
        float sum = 0.f;
        #pragma unroll
        for (int j = 0; j < 64; j++) {
            float e = __expf(sim[j] - m);
            sim[j] = e; sum += e;
        }
        float inv = 1.f / sum;
        u64 o2[4] = {0ull, 0ull, 0ull, 0ull};
        #pragma unroll
        for (int j = 0; j < 64; j++) {
            ulonglong2 v0 = *(const ulonglong2*)&vs[j][hq * 8];
            ulonglong2 v1 = *(const ulonglong2*)&vs[j][hq * 8 + 4];
            u64 pb = pack2(sim[j], sim[j]);
            o2[0] = fma2(pb, v0.x, o2[0]);
            o2[1] = fma2(pb, v0.y, o2[1]);
            o2[2] = fma2(pb, v1.x, o2[2]);
            o2[3] = fma2(pb, v1.y, o2[3]);
        }
        float2 r0 = unpk(o2[0]), r1 = unpk(o2[1]), r2 = unpk(o2[2]), r3 = unpk(o2[3]);
        int ir = i >> 3, jc = i & 7;
        size_t pix = ((size_t)(b * 256 + hb * 8 + ir) * 256) + (wb * 8 + jc);
        float4* op = (float4*)(g_x1 + pix * 32 + hq * 8);
        op[0] = make_float4(r0.x * inv, r0.y * inv, r1.x * inv, r1.y * inv);
        op[1] = make_float4(r2.x * inv, r2.y * inv, r3.x * inv, r3.y * inv);
    }
}

// ---------------- forward row rFFT, 2 real channels per complex warp-FFT --------
// block = (b, row, group of 16 ch); 4096 blocks, 256 threads (8 warps = 8 FFTs)
__global__ __launch_bounds__(256) void rowfft_kernel(const float* __restrict__ x)
{
    __shared__ float2 sbuf[8 * 256];
    int t  = threadIdx.x;
    int lane = t & 31, w = t >> 5;
    int bx = blockIdx.x;
    int b   = bx >> 9;
    int row = (bx >> 1) & 255;
    int g   = bx & 1;

    const float* xp = x + ((size_t)(b * 256 + row) * 256) * 64 + 32 + g * 16;
    #pragma unroll
    for (int e = 0; e < 8; e++) {
        int l = t + e * 256;
        int n = l >> 3;
        int f = l & 7;
        sbuf[f * 256 + zin(n, f)] = *(const float2*)(xp + (size_t)n * 64 + 2 * f);
    }
    __syncthreads();

    float2 v[8];
    #pragma unroll
    for (int m2 = 0; m2 < 8; m2++) v[m2] = sbuf[w * 256 + zin(lane + 32 * m2, w)];
    warp_fft256_fwd(v, lane);

    int p = rev5(lane);
    const int Q[8] = {0, 4, 2, 6, 1, 5, 3, 7};
    #pragma unroll
    for (int r = 0; r < 8; r++) sbuf[w * 256 + zq(Q[r], p)] = v[r];
    __syncthreads();

    int img0 = b * 32 + g * 16;
    if (t < 129) {
        int m = (256 - t) & 255;
        int pt = zpos(t), pm = zpos(m);
        #pragma unroll
        for (int f = 0; f < 8; f++) {
            float2 zk = sbuf[f * 256 + pt];
            float2 zm = sbuf[f * 256 + pm];
            float2 A  = make_float2(0.5f * (zk.x + zm.x), 0.5f * (zk.y - zm.y));
            float2 Bv = make_float2(0.5f * (zk.y + zm.y), 0.5f * (zm.x - zk.x));
            size_t o = ((size_t)(img0 + 2 * f) * 256 + row) * 129 + t;
            g_spec[o] = A;
            g_spec[o + (size_t)256 * 129] = Bv;
        }
    }
}

// ---------------- column FFT + amp/phase transform + column IFFT ---------------
// block = (k-group of 8, img); grid (17, 256); warp w handles k = k0 + w
__global__ __launch_bounds__(256) void coltrans_kernel(
    const float* __restrict__ amp_w, const float* __restrict__ amp_b,
    const float* __restrict__ pha_w, const float* __restrict__ pha_b)
{
    __shared__ float2 sbuf[8 * 256];
    int t   = threadIdx.x;
    int lane = t & 31, w = t >> 5;
    int img = blockIdx.y;
    int k0  = blockIdx.x * 8;
    int ch  = img & 31;

    float aw = amp_w[ch], ab = amp_b[ch], pw = pha_w[ch], pb = pha_b[ch];

    size_t base = (size_t)img * 256 * 129;
    #pragma unroll
    for (int e = 0; e < 8; e++) {
        int l = t + e * 256;
        int row = l >> 3;
        int kk  = l & 7;
        int k   = k0 + kk;
        float2 vv = make_float2(0.f, 0.f);
        if (k < 129) vv = g_spec[base + (size_t)row * 129 + k];
        sbuf[kk * 256 + zin(row, kk)] = vv;
    }
    __syncthreads();

    float2 v[8];
    #pragma unroll
    for (int m2 = 0; m2 < 8; m2++) v[m2] = sbuf[w * 256 + zin(lane + 32 * m2, w)];
    warp_fft256_fwd(v, lane);

    // pointwise amp/phase affine (order-agnostic; in registers)
    #pragma unroll
    for (int m2 = 0; m2 < 8; m2++) {
        float2 vv = v[m2];
        float amp = sqrtf(vv.x * vv.x + vv.y * vv.y);
        float pha = atan2f(vv.y, vv.x);
        float af = amp * aw + ab;
        float pf = pha * pw + pb;
        float sn, cs; __sincosf(pf, &sn, &cs);
        v[m2] = make_float2(af * cs + 2e-8f, af * sn + 1e-8f);
    }

    warp_fft256_inv(v, lane);
    #pragma unroll
    for (int m2 = 0; m2 < 8; m2++) sbuf[w * 256 + zin(lane + 32 * m2, w)] = v[m2];
    __syncthreads();

    #pragma unroll
    for (int e = 0; e < 8; e++) {
        int l = t + e * 256;
        int row = l >> 3;
        int kk  = l & 7;
        int k   = k0 + kk;
        if (k < 129) g_spec[base + (size_t)row * 129 + k] = sbuf[kk * 256 + zin(row, kk)];
    }
}

// ---------------- inverse row irFFT + abs, 2 image planes per warp-FFT ----------
// block = (img-pair, row-group of 8); 4096 blocks; warp w handles row row0+w
__global__ __launch_bounds__(256) void rowifft_kernel()
{
    __shared__ float2 sbuf[8 * 256];
    int t  = threadIdx.x;
    int lane = t & 31, w = t >> 5;
    int bx = blockIdx.x;
    int pr   = bx >> 5;
    int row0 = (bx & 31) * 8;
    int imgA = 2 * pr;

    size_t baseA = ((size_t)imgA * 256 + row0) * 129;
    size_t baseB = baseA + (size_t)256 * 129;
    if (t < 129) {
        bool edge = (t == 0) || (t == 128);
        int pt = zpos(t), pm = zpos((256 - t) & 255);
        #pragma unroll
        for (int f = 0; f < 8; f++) {
            float2 A  = g_spec[baseA + (size_t)f * 129 + t];
            float2 Bv = g_spec[baseB + (size_t)f * 129 + t];
            if (edge) { A.y = 0.f; Bv.y = 0.f; }   // irfft discards Im at DC/Nyquist
            sbuf[f * 256 + pt] = make_float2(A.x - Bv.y, A.y + Bv.x);
            if (t >= 1 && t < 128)
                sbuf[f * 256 + pm] = make_float2(A.x + Bv.y, Bv.x - A.y);
        }
    }
    __syncthreads();

    float2 v[8];
    int p = rev5(lane);
    const int Q[8] = {0, 4, 2, 6, 1, 5, 3, 7};
    #pragma unroll
    for (int r = 0; r < 8; r++) v[r] = sbuf[w * 256 + zq(Q[r], p)];
    warp_fft256_inv(v, lane);

    size_t oA = ((size_t)imgA * 256 + row0 + w) * 256;
    #pragma unroll
    for (int m2 = 0; m2 < 8; m2++) {
        int n = lane + 32 * m2;
        g_x2[oA + n]         = fabsf(v[m2].x * (1.f / 65536.f));
        g_x2[oA + 65536 + n] = fabsf(v[m2].y * (1.f / 65536.f));
    }
}

// ---------------- projection (unchanged, working) ----------------
__global__ __launch_bounds__(64) void proj_kernel(
    const float* __restrict__ pw, const float* __restrict__ pbias,
    float* __restrict__ out)
{
    __shared__ float WsT[64][68];
    __shared__ float x1s[32][68];
    __shared__ float x2s[32][68];
    int t  = threadIdx.x;
    int p0 = blockIdx.x * 64;
    int b    = p0 >> 16;
    int rem0 = p0 & 65535;

    #pragma unroll
    for (int e = 0; e < 64; e++) WsT[t][e] = pw[e * 64 + t];
    #pragma unroll
    for (int e = 0; e < 32; e++) {
        int l = e * 64 + t;
        x1s[l & 31][l >> 5] = g_x1[(size_t)p0 * 32 + l];
    }
    {
        size_t xb = (size_t)b * 2097152 + rem0;
        #pragma unroll
        for (int e = 0; e < 32; e++)
            x2s[e][t] = g_x2[xb + (size_t)e * 65536 + t];
    }
    __syncthreads();

    int pg    = t >> 2;
    int dbase = (t & 3) << 4;
    u64 acc[4][8];
    #pragma unroll
    for (int k = 0; k < 8; k++) {
        u64 bp = *(const u64*)&pbias[dbase + 2 * k];
        #pragma unroll
        for (int p = 0; p < 4; p++) acc[p][k] = bp;
    }

    #pragma unroll
    for (int c = 0; c < 32; c++) {
        float4 a  = *(const float4*)&x1s[c][pg * 4];
        float4 b2 = *(const float4*)&x2s[c][pg * 4];
        u64 ax[4] = {pack2(a.x, a.x),   pack2(a.y, a.y),   pack2(a.z, a.z),   pack2(a.w, a.w)};
        u64 bx[4] = {pack2(b2.x, b2.x), pack2(b2.y, b2.y), pack2(b2.z, b2.z), pack2(b2.w, b2.w)};
        ulonglong2 wA0 = *(const ulonglong2*)&WsT[c][dbase];
        ulonglong2 wA1 = *(const ulonglong2*)&WsT[c][dbase + 4];
        ulonglong2 wA2 = *(const ulonglong2*)&WsT[c][dbase + 8];
        ulonglong2 wA3 = *(const ulonglong2*)&WsT[c][dbase + 12];
        ulonglong2 wB0 = *(const ulonglong2*)&WsT[32 + c][dbase];
        ulonglong2 wB1 = *(const ulonglong2*)&WsT[32 + c][dbase + 4];
        ulonglong2 wB2 = *(const ulonglong2*)&WsT[32 + c][dbase + 8];
        ulonglong2 wB3 = *(const ulonglong2*)&WsT[32 + c][dbase + 12];
        u64 w1[8] = {wA0.x, wA0.y, wA1.x, wA1.y, wA2.x, wA2.y, wA3.x, wA3.y};
        u64 w2[8] = {wB0.x, wB0.y, wB1.x, wB1.y, wB2.x, wB2.y, wB3.x, wB3.y};
        #pragma unroll
        for (int k = 0; k < 8; k++) {
            #pragma unroll
            for (int p = 0; p < 4; p++) {
                acc[p][k] = fma2(ax[p], w1[k], acc[p][k]);
                acc[p][k] = fma2(bx[p], w2[k], acc[p][k]);
            }
        }
    }

    #pragma unroll
    for (int p = 0; p < 4; p++) {
        float* o = out + (size_t)(p0 + pg * 4 + p) * 64 + dbase;
        #pragma unroll
        for (int k = 0; k < 4; k++) {
            float2 lo = unpk(acc[p][2 * k]);
            float2 hi = unpk(acc[p][2 * k + 1]);
            *(float4*)&o[4 * k] = make_float4(lo.x, lo.y, hi.x, hi.y);
        }
    }
}

// ---------------- launch ----------------
extern "C" void kernel_launch(void* const* d_in, const int* in_sizes, int n_in,
                              void* d_out, int out_size)
{
    const float* x      = (const float*)d_in[0];
    const float* w_qkv  = (const float*)d_in[1];
    const float* b_qkv  = (const float*)d_in[2];
    const float* pos    = (const float*)d_in[3];
    const float* amp_w  = (const float*)d_in[4];
    const float* amp_b  = (const float*)d_in[5];
    const float* pha_w  = (const float*)d_in[6];
    const float* pha_b  = (const float*)d_in[7];
    const float* proj_w = (const float*)d_in[8];
    const float* proj_b = (const float*)d_in[9];
    float* out = (float*)d_out;

    transpose_pos_kernel<<<64, 256>>>(pos);
    attn_kernel<<<8192, 256>>>(x, w_qkv, b_qkv);
    rowfft_kernel<<<4096, 256>>>(x);
    coltrans_kernel<<<dim3(17, 256), 256>>>(amp_w, amp_b, pha_w, pha_b);
    rowifft_kernel<<<4096, 256>>>();
    proj_kernel<<<8192, 64>>>(proj_w, proj_b, out);
}

// round 10
// speedup vs baseline: 1.0406x; 1.0406x over previous
#include <cuda_runtime.h>
#include <cstdint>

#define PI_F 3.14159265358979323846f
typedef unsigned long long u64;

// ---------------- scratch (device globals; no runtime allocation) ----------------
__device__ float2 g_spec[256u * 256u * 129u];      // [img=b*32+ch][row][k] spectrum
__device__ float  g_x1[8u * 256u * 256u * 32u];    // [pix][32] local-mixer out
__device__ float  g_x2[256u * 256u * 256u];        // [img][row][w] global-mixer out
__device__ float  g_posT[4 * 64 * 64];             // pos transposed: [h][j][i]

// ---------------- packed f32x2 helpers ----------------
__device__ __forceinline__ u64 fma2(u64 a, u64 b, u64 c) {
    u64 d; asm("fma.rn.f32x2 %0, %1, %2, %3;" : "=l"(d) : "l"(a), "l"(b), "l"(c)); return d;
}
__device__ __forceinline__ u64 add2(u64 a, u64 b) {
    u64 d; asm("add.rn.f32x2 %0, %1, %2;" : "=l"(d) : "l"(a), "l"(b)); return d;
}
__device__ __forceinline__ u64 mul2(u64 a, u64 b) {
    u64 d; asm("mul.rn.f32x2 %0, %1, %2;" : "=l"(d) : "l"(a), "l"(b)); return d;
}
__device__ __forceinline__ u64 pack2(float lo, float hi) {
    u64 r; asm("mov.b64 %0, {%1, %2};" : "=l"(r) : "f"(lo), "f"(hi)); return r;
}
__device__ __forceinline__ float2 unpk(u64 v) {
    float2 r; asm("mov.b64 {%0, %1}, %2;" : "=f"(r.x), "=f"(r.y) : "l"(v)); return r;
}
__device__ __forceinline__ u64 swap2(u64 a) {      // (x,y) -> (y,x); register renames
    float2 f = unpk(a); return pack2(f.y, f.x);
}
__device__ __forceinline__ float2 cmulf(float2 a, float2 b) {
    return make_float2(a.x * b.x - a.y * b.y, a.x * b.y + a.y * b.x);
}
// complex a * (c + i s), packed: c2 = (c,c), s2m = (-s, s)
__device__ __forceinline__ u64 rotu(u64 a, u64 c2, u64 s2m) {
    return fma2(swap2(a), s2m, mul2(a, c2));
}
__device__ __forceinline__ int rev5(int l) {
    return ((l & 1) << 4) | ((l & 2) << 2) | (l & 4) | ((l & 8) >> 2) | ((l & 16) >> 4);
}
// smem index maps (conflict-free by construction)
__device__ __forceinline__ int zin(int n, int f) { return n ^ (4 * f); }            // natural staging
__device__ __forceinline__ int zq(int q, int p)  { return q * 32 + (p ^ (4 * q)); } // spectral (q,p)
__device__ __forceinline__ int zpos(int k)       { return zq(k & 7, k >> 3); }      // spectral by k

// ---------------- warp-level 256-pt FFT, packed f32x2, branchless ----------------
// forward: natural (lane l, reg m holds x[l+32m]) -> spectral: (reg r, lane l)
// holds X[k], k = Q[r] + 8*rev5(l), Q = {0,4,2,6,1,5,3,7}. inverse = reverse.

template <int SIGN>
__device__ __forceinline__ void reg_fft8_dif(u64 v[8], u64 neg1) {
    const float S = (float)SIGN;
    const float C = 0.70710678118654752f;
    u64 cC  = pack2(C, C);
    u64 cCn = pack2(-C, -C);
    u64 sSC = pack2(-S * C, S * C);
    u64 iS  = pack2(-S, S);
    // h=4
    {
        u64 t0 = fma2(v[4], neg1, v[0]);
        u64 t1 = fma2(v[5], neg1, v[1]);
        u64 t2 = fma2(v[6], neg1, v[2]);
        u64 t3 = fma2(v[7], neg1, v[3]);
        v[0] = add2(v[0], v[4]); v[1] = add2(v[1], v[5]);
        v[2] = add2(v[2], v[6]); v[3] = add2(v[3], v[7]);
        v[4] = t0;
        v[5] = rotu(t1, cC, sSC);
        v[6] = mul2(swap2(t2), iS);
        v[7] = rotu(t3, cCn, sSC);
    }
    // h=2
    #pragma unroll
    for (int b = 0; b < 8; b += 4) {
        u64 u0 = fma2(v[b + 2], neg1, v[b]);
        u64 u1 = fma2(v[b + 3], neg1, v[b + 1]);
        v[b]     = add2(v[b], v[b + 2]);
        v[b + 1] = add2(v[b + 1], v[b + 3]);
        v[b + 2] = u0;
        v[b + 3] = mul2(swap2(u1), iS);
    }
    // h=1
    #pragma unroll
    for (int b = 0; b < 8; b += 2) {
        u64 a = v[b], c = v[b + 1];
        v[b] = add2(a, c);
        v[b + 1] = fma2(c, neg1, a);
    }
}

template <int SIGN>
__device__ __forceinline__ void reg_fft8_dit(u64 v[8], u64 neg1) {
    const float S = (float)SIGN;
    const float C = 0.70710678118654752f;
    u64 cC  = pack2(C, C);
    u64 cCn = pack2(-C, -C);
    u64 sSC = pack2(-S * C, S * C);
    u64 iS  = pack2(-S, S);
    // d=1
    #pragma unroll
    for (int b = 0; b < 8; b += 2) {
        u64 a = v[b], c = v[b + 1];
        v[b] = add2(a, c);
        v[b + 1] = fma2(c, neg1, a);
    }
    // d=2
    #pragma unroll
    for (int b = 0; b < 8; b += 4) {
        u64 t0 = v[b + 2];
        u64 t1 = mul2(swap2(v[b + 3]), iS);
        u64 a0 = v[b], a1 = v[b + 1];
        v[b]     = add2(a0, t0); v[b + 2] = fma2(t0, neg1, a0);
        v[b + 1] = add2(a1, t1); v[b + 3] = fma2(t1, neg1, a1);
    }
    // d=4
    {
        u64 t0 = v[4];
        u64 t1 = rotu(v[5], cC, sSC);
        u64 t2 = mul2(swap2(v[6]), iS);
        u64 t3 = rotu(v[7], cCn, sSC);
        u64 a0 = v[0], a1 = v[1], a2 = v[2], a3 = v[3];
        v[0] = add2(a0, t0); v[4] = fma2(t0, neg1, a0);
        v[1] = add2(a1, t1); v[5] = fma2(t1, neg1, a1);
        v[2] = add2(a2, t2); v[6] = fma2(t2, neg1, a2);
        v[3] = add2(a3, t3); v[7] = fma2(t3, neg1, a3);
    }
}

template <int SIGN>
__device__ __forceinline__ void mid_twiddle(u64 v[8], int lane) {
    // v[r] *= W256^{SIGN * lane * Q[r]}, Q = {0,4,2,6,1,5,3,7}
    float ang = (float)SIGN * (2.0f * PI_F / 256.0f) * (float)lane;
    float sn, cs; __sincosf(ang, &sn, &cs);
    float2 w1 = make_float2(cs, sn);
    float2 w2 = cmulf(w1, w1);
    float2 w3 = cmulf(w2, w1);
    float2 w4 = cmulf(w2, w2);
    float2 w5 = cmulf(w4, w1);
    float2 w6 = cmulf(w4, w2);
    float2 w7 = cmulf(w4, w3);
    v[1] = rotu(v[1], pack2(w4.x, w4.x), pack2(-w4.y, w4.y));
    v[2] = rotu(v[2], pack2(w2.x, w2.x), pack2(-w2.y, w2.y));
    v[3] = rotu(v[3], pack2(w6.x, w6.x), pack2(-w6.y, w6.y));
    v[4] = rotu(v[4], pack2(w1.x, w1.x), pack2(-w1.y, w1.y));
    v[5] = rotu(v[5], pack2(w5.x, w5.x), pack2(-w5.y, w5.y));
    v[6] = rotu(v[6], pack2(w3.x, w3.x), pack2(-w3.y, w3.y));
    v[7] = rotu(v[7], pack2(w7.x, w7.x), pack2(-w7.y, w7.y));
}

template <int SIGN>
__device__ __forceinline__ void lane_fft_dif(u64 v[8], int lane) {
    #pragma unroll
    for (int h = 16; h >= 1; h >>= 1) {
        int j = lane & (h - 1);
        float ang = (float)SIGN * (2.0f * PI_F / 32.0f) * (float)(j * (16 / h));
        float sn, cs; __sincosf(ang, &sn, &cs);
        bool up = (lane & h) != 0;
        float twc = up ? cs : 1.0f;
        float tws = up ? sn : 0.0f;
        float sg  = up ? -1.0f : 1.0f;
        u64 sg2 = pack2(sg, sg);
        u64 c2  = pack2(twc, twc);
        u64 s2m = pack2(-tws, tws);
        #pragma unroll
        for (int r = 0; r < 8; r++) {
            float2 f = unpk(v[r]);
            float ox = __shfl_xor_sync(0xffffffffu, f.x, h);
            float oy = __shfl_xor_sync(0xffffffffu, f.y, h);
            u64 u = fma2(sg2, v[r], pack2(ox, oy));   // lower: v+o ; upper: o−v
            v[r] = rotu(u, c2, s2m);                  // lower twiddle = (1,0)
        }
    }
}

template <int SIGN>
__device__ __forceinline__ void lane_fft_dit(u64 v[8], int lane) {
    #pragma unroll
    for (int d = 1; d <= 16; d <<= 1) {
        int j = lane & (d - 1);
        float ang = (float)SIGN * (2.0f * PI_F / 32.0f) * (float)(j * (16 / d));
        float sn, cs; __sincosf(ang, &sn, &cs);
        bool up = (lane & d) != 0;
        float twc = up ? cs : 1.0f;
        float tws = up ? sn : 0.0f;
        float sg  = up ? -1.0f : 1.0f;
        u64 sg2 = pack2(sg, sg);
        u64 c2  = pack2(twc, twc);
        u64 s2m = pack2(-tws, tws);
        #pragma unroll
        for (int r = 0; r < 8; r++) {
            u64 rv = rotu(v[r], c2, s2m);             // identity on lower lanes
            float2 f = unpk(rv);
            float ox = __shfl_xor_sync(0xffffffffu, f.x, d);
            float oy = __shfl_xor_sync(0xffffffffu, f.y, d);
            v[r] = fma2(sg2, rv, pack2(ox, oy));      // lower: rv+o ; upper: o−rv
        }
    }
}

__device__ __forceinline__ void warp_fft256_fwd(u64 v[8], int lane, u64 neg1) {
    reg_fft8_dif<-1>(v, neg1);
    mid_twiddle<-1>(v, lane);
    lane_fft_dif<-1>(v, lane);
}
__device__ __forceinline__ void warp_fft256_inv(u64 v[8], int lane, u64 neg1) {
    lane_fft_dit<1>(v, lane);
    mid_twiddle<1>(v, lane);
    reg_fft8_dit<1>(v, neg1);
}

// ---------------- pos transpose (tiny, once per launch) ----------------
__global__ __launch_bounds__(256) void transpose_pos_kernel(const float* __restrict__ pos)
{
    int idx = blockIdx.x * 256 + threadIdx.x;
    int h = idx >> 12;
    int j = (idx >> 6) & 63;
    int i = idx & 63;
    g_posT[idx] = pos[((h * 64) + i) * 64 + j];
}

// ---------------- local mixer: window attention (unchanged, working) ----------------
__global__ __launch_bounds__(256) void attn_kernel(
    const float* __restrict__ x, const float* __restrict__ wqkv,
    const float* __restrict__ bqkv)
{
    __shared__ float xw[64][36];
    __shared__ float wq[96][36];
    __shared__ float bq[96];
    __shared__ float ks[64][36];
    __shared__ float vs[64][36];

    int t = threadIdx.x;
    int wid = blockIdx.x;
    int b   = wid >> 10;
    int hb  = (wid >> 5) & 31;
    int wb  = wid & 31;

    {
        const float4* xv = (const float4*)x;
        #pragma unroll
        for (int e = 0; e < 2; e++) {
            int l = t + e * 256;
            int n = l >> 3;
            int q4 = l & 7;
            int i = n >> 3, j = n & 7;
            size_t pix = ((size_t)(b * 256 + hb * 8 + i) * 256) + (wb * 8 + j);
            *(float4*)&xw[n][q4 * 4] = xv[pix * 16 + q4];
        }
        #pragma unroll
        for (int e = 0; e < 12; e++) {
            int l = t + e * 256;
            wq[l >> 5][l & 31] = wqkv[l];
        }
        if (t < 96) bq[t] = bqkv[t];
    }
    __syncthreads();

    int i  = t & 63;
    int hq = t >> 6;

    u64 xr[16];
    #pragma unroll
    for (int c = 0; c < 8; c++) {
        ulonglong2 v = *(const ulonglong2*)&xw[i][4 * c];
        xr[2 * c] = v.x; xr[2 * c + 1] = v.y;
    }

    u64 q2[4];
    #pragma unroll
    for (int kind = 0; kind < 3; kind++) {
        float o[8];
        #pragma unroll
        for (int dd = 0; dd < 8; dd++) {
            int d = kind * 32 + hq * 8 + dd;
            const float* wrow = &wq[d][0];
            u64 a0 = 0ull, a1 = 0ull;
            #pragma unroll
            for (int c = 0; c < 4; c++) {
                ulonglong2 w0 = *(const ulonglong2*)(wrow + 8 * c);
                ulonglong2 w1 = *(const ulonglong2*)(wrow + 8 * c + 4);
                a0 = fma2(xr[4 * c],     w0.x, a0);
                a1 = fma2(xr[4 * c + 1], w0.y, a1);
                a0 = fma2(xr[4 * c + 2], w1.x, a0);
                a1 = fma2(xr[4 * c + 3], w1.y, a1);
            }
            float2 p = unpk(a0), q = unpk(a1);
            o[dd] = p.x + p.y + q.x + q.y + bq[d];
        }
        if (kind == 0) {
            #pragma unroll
            for (int c = 0; c < 4; c++)
                q2[c] = pack2(o[2 * c]     * 0.35355339059327373f,
                              o[2 * c + 1] * 0.35355339059327373f);
        } else if (kind == 1) {
            *(float4*)&ks[i][hq * 8]     = make_float4(o[0], o[1], o[2], o[3]);
            *(float4*)&ks[i][hq * 8 + 4] = make_float4(o[4], o[5], o[6], o[7]);
        } else {
            *(float4*)&vs[i][hq * 8]     = make_float4(o[0], o[1], o[2], o[3]);
            *(float4*)&vs[i][hq * 8 + 4] = make_float4(o[4], o[5], o[6], o[7]);
        }
    }
    __syncthreads();

    {
        const float* pT = g_posT + hq * 4096 + i;
        float sim[64];
        float m = -1e30f;
        #pragma unroll
        for (int j = 0; j < 64; j++) {
            ulonglong2 k0 = *(const ulonglong2*)&ks[j][hq * 8];
            ulonglong2 k1 = *(const ulonglong2*)&ks[j][hq * 8 + 4];
            u64 a = 0ull;
            a = fma2(q2[0], k0.x, a);
            a = fma2(q2[1], k0.y, a);
            a = fma2(q2[2], k1.x, a);
            a = fma2(q2[3], k1.y, a);
            float2 p = unpk(a);
            float s = p.x + p.y + pT[j * 64];
            sim[j] = s;
            m = fmaxf(m, s);
        }
        float sum = 0.f;
        #pragma unroll
        for (int j = 0; j < 64; j++) {
            float e = __expf(sim[j] - m);
            sim[j] = e; sum += e;
        }
        float inv = 1.f / sum;
        u64 o2[4] = {0ull, 0ull, 0ull, 0ull};
        #pragma unroll
        for (int j = 0; j < 64; j++) {
            ulonglong2 v0 = *(const ulonglong2*)&vs[j][hq * 8];
            ulonglong2 v1 = *(const ulonglong2*)&vs[j][hq * 8 + 4];
            u64 pb = pack2(sim[j], sim[j]);
            o2[0] = fma2(pb, v0.x, o2[0]);
            o2[1] = fma2(pb, v0.y, o2[1]);
            o2[2] = fma2(pb, v1.x, o2[2]);
            o2[3] = fma2(pb, v1.y, o2[3]);
        }
        float2 r0 = unpk(o2[0]), r1 = unpk(o2[1]), r2 = unpk(o2[2]), r3 = unpk(o2[3]);
        int ir = i >> 3, jc = i & 7;
        size_t pix = ((size_t)(b * 256 + hb * 8 + ir) * 256) + (wb * 8 + jc);
        float4* op = (float4*)(g_x1 + pix * 32 + hq * 8);
        op[0] = make_float4(r0.x * inv, r0.y * inv, r1.x * inv, r1.y * inv);
        op[1] = make_float4(r2.x * inv, r2.y * inv, r3.x * inv, r3.y * inv);
    }
}

// ---------------- forward row rFFT, 2 real channels per complex warp-FFT --------
// block = (b, row, group of 16 ch); 4096 blocks, 256 threads (8 warps = 8 FFTs)
__global__ __launch_bounds__(256, 4) void rowfft_kernel(const float* __restrict__ x)
{
    __shared__ float2 sbuf[8 * 256];
    u64* sb = (u64*)sbuf;
    int t  = threadIdx.x;
    int lane = t & 31, w = t >> 5;
    int bx = blockIdx.x;
    int b   = bx >> 9;
    int row = (bx >> 1) & 255;
    int g   = bx & 1;
    u64 neg1 = pack2(-1.f, -1.f);

    const float* xp = x + ((size_t)(b * 256 + row) * 256) * 64 + 32 + g * 16;
    #pragma unroll
    for (int e = 0; e < 8; e++) {
        int l = t + e * 256;
        int n = l >> 3;
        int f = l & 7;
        sb[f * 256 + zin(n, f)] = *(const u64*)(xp + (size_t)n * 64 + 2 * f);
    }
    __syncthreads();

    u64 v[8];
    #pragma unroll
    for (int m2 = 0; m2 < 8; m2++) v[m2] = sb[w * 256 + zin(lane + 32 * m2, w)];
    warp_fft256_fwd(v, lane, neg1);

    int p = rev5(lane);
    const int Q[8] = {0, 4, 2, 6, 1, 5, 3, 7};
    #pragma unroll
    for (int r = 0; r < 8; r++) sb[w * 256 + zq(Q[r], p)] = v[r];
    __syncthreads();

    int img0 = b * 32 + g * 16;
    if (t < 129) {
        int m = (256 - t) & 255;
        int pt = zpos(t), pm = zpos(m);
        #pragma unroll
        for (int f = 0; f < 8; f++) {
            float2 zk = sbuf[f * 256 + pt];
            float2 zm = sbuf[f * 256 + pm];
            float2 A  = make_float2(0.5f * (zk.x + zm.x), 0.5f * (zk.y - zm.y));
            float2 Bv = make_float2(0.5f * (zk.y + zm.y), 0.5f * (zm.x - zk.x));
            size_t o = ((size_t)(img0 + 2 * f) * 256 + row) * 129 + t;
            g_spec[o] = A;
            g_spec[o + (size_t)256 * 129] = Bv;
        }
    }
}

// ---------------- column FFT + amp/phase transform + column IFFT ---------------
// block = (k-group of 8, img); grid (17, 256); warp w handles k = k0 + w
__global__ __launch_bounds__(256, 4) void coltrans_kernel(
    const float* __restrict__ amp_w, const float* __restrict__ amp_b,
    const float* __restrict__ pha_w, const float* __restrict__ pha_b)
{
    __shared__ float2 sbuf[8 * 256];
    u64* sb = (u64*)sbuf;
    int t   = threadIdx.x;
    int lane = t & 31, w = t >> 5;
    int img = blockIdx.y;
    int k0  = blockIdx.x * 8;
    int ch  = img & 31;
    u64 neg1 = pack2(-1.f, -1.f);

    float aw = amp_w[ch], ab = amp_b[ch], pw = pha_w[ch], pb = pha_b[ch];

    size_t base = (size_t)img * 256 * 129;
    #pragma unroll
    for (int e = 0; e < 8; e++) {
        int l = t + e * 256;
        int row = l >> 3;
        int kk  = l & 7;
        int k   = k0 + kk;
        float2 vv = make_float2(0.f, 0.f);
        if (k < 129) vv = g_spec[base + (size_t)row * 129 + k];
        sbuf[kk * 256 + zin(row, kk)] = vv;
    }
    __syncthreads();

    u64 v[8];
    #pragma unroll
    for (int m2 = 0; m2 < 8; m2++) v[m2] = sb[w * 256 + zin(lane + 32 * m2, w)];
    warp_fft256_fwd(v, lane, neg1);

    // pointwise amp/phase affine (order-agnostic; in registers)
    #pragma unroll
    for (int m2 = 0; m2 < 8; m2++) {
        float2 vv = unpk(v[m2]);
        float amp = sqrtf(vv.x * vv.x + vv.y * vv.y);
        float pha = atan2f(vv.y, vv.x);
        float af = amp * aw + ab;
        float pf = pha * pw + pb;
        float sn, cs; __sincosf(pf, &sn, &cs);
        v[m2] = pack2(af * cs + 2e-8f, af * sn + 1e-8f);
    }

    warp_fft256_inv(v, lane, neg1);
    #pragma unroll
    for (int m2 = 0; m2 < 8; m2++) sb[w * 256 + zin(lane + 32 * m2, w)] = v[m2];
    __syncthreads();

    #pragma unroll
    for (int e = 0; e < 8; e++) {
        int l = t + e * 256;
        int row = l >> 3;
        int kk  = l & 7;
        int k   = k0 + kk;
        if (k < 129) g_spec[base + (size_t)row * 129 + k] = sbuf[kk * 256 + zin(row, kk)];
    }
}

// ---------------- inverse row irFFT + abs, 2 image planes per warp-FFT ----------
// block = (img-pair, row-group of 8); 4096 blocks; warp w handles row row0+w
__global__ __launch_bounds__(256, 4) void rowifft_kernel()
{
    __shared__ float2 sbuf[8 * 256];
    u64* sb = (u64*)sbuf;
    int t  = threadIdx.x;
    int lane = t & 31, w = t >> 5;
    int bx = blockIdx.x;
    int pr   = bx >> 5;
    int row0 = (bx & 31) * 8;
    int imgA = 2 * pr;
    u64 neg1 = pack2(-1.f, -1.f);

    size_t baseA = ((size_t)imgA * 256 + row0) * 129;
    size_t baseB = baseA + (size_t)256 * 129;
    if (t < 129) {
        bool edge = (t == 0) || (t == 128);
        int pt = zpos(t), pm = zpos((256 - t) & 255);
        #pragma unroll
        for (int f = 0; f < 8; f++) {
            float2 A  = g_spec[baseA + (size_t)f * 129 + t];
            float2 Bv = g_spec[baseB + (size_t)f * 129 + t];
            if (edge) { A.y = 0.f; Bv.y = 0.f; }   // irfft discards Im at DC/Nyquist
            sbuf[f * 256 + pt] = make_float2(A.x - Bv.y, A.y + Bv.x);
            if (t >= 1 && t < 128)
                sbuf[f * 256 + pm] = make_float2(A.x + Bv.y, Bv.x - A.y);
        }
    }
    __syncthreads();

    u64 v[8];
    int p = rev5(lane);
    const int Q[8] = {0, 4, 2, 6, 1, 5, 3, 7};
    #pragma unroll
    for (int r = 0; r < 8; r++) v[r] = sb[w * 256 + zq(Q[r], p)];
    warp_fft256_inv(v, lane, neg1);

    size_t oA = ((size_t)imgA * 256 + row0 + w) * 256;
    #pragma unroll
    for (int m2 = 0; m2 < 8; m2++) {
        int n = lane + 32 * m2;
        float2 f = unpk(v[m2]);
        g_x2[oA + n]         = fabsf(f.x * (1.f / 65536.f));
        g_x2[oA + 65536 + n] = fabsf(f.y * (1.f / 65536.f));
    }
}

// ---------------- projection (unchanged, working) ----------------
__global__ __launch_bounds__(64) void proj_kernel(
    const float* __restrict__ pw, const float* __restrict__ pbias,
    float* __restrict__ out)
{
    __shared__ float WsT[64][68];
    __shared__ float x1s[32][68];
    __shared__ float x2s[32][68];
    int t  = threadIdx.x;
    int p0 = blockIdx.x * 64;
    int b    = p0 >> 16;
    int rem0 = p0 & 65535;

    #pragma unroll
    for (int e = 0; e < 64; e++) WsT[t][e] = pw[e * 64 + t];
    #pragma unroll
    for (int e = 0; e < 32; e++) {
        int l = e * 64 + t;
        x1s[l & 31][l >> 5] = g_x1[(size_t)p0 * 32 + l];
    }
    {
        size_t xb = (size_t)b * 2097152 + rem0;
        #pragma unroll
        for (int e = 0; e < 32; e++)
            x2s[e][t] = g_x2[xb + (size_t)e * 65536 + t];
    }
    __syncthreads();

    int pg    = t >> 2;
    int dbase = (t & 3) << 4;
    u64 acc[4][8];
    #pragma unroll
    for (int k = 0; k < 8; k++) {
        u64 bp = *(const u64*)&pbias[dbase + 2 * k];
        #pragma unroll
        for (int p = 0; p < 4; p++) acc[p][k] = bp;
    }

    #pragma unroll
    for (int c = 0; c < 32; c++) {
        float4 a  = *(const float4*)&x1s[c][pg * 4];
        float4 b2 = *(const float4*)&x2s[c][pg * 4];
        u64 ax[4] = {pack2(a.x, a.x),   pack2(a.y, a.y),   pack2(a.z, a.z),   pack2(a.w, a.w)};
        u64 bx[4] = {pack2(b2.x, b2.x), pack2(b2.y, b2.y), pack2(b2.z, b2.z), pack2(b2.w, b2.w)};
        ulonglong2 wA0 = *(const ulonglong2*)&WsT[c][dbase];
        ulonglong2 wA1 = *(const ulonglong2*)&WsT[c][dbase + 4];
        ulonglong2 wA2 = *(const ulonglong2*)&WsT[c][dbase + 8];
        ulonglong2 wA3 = *(const ulonglong2*)&WsT[c][dbase + 12];
        ulonglong2 wB0 = *(const ulonglong2*)&WsT[32 + c][dbase];
        ulonglong2 wB1 = *(const ulonglong2*)&WsT[32 + c][dbase + 4];
        ulonglong2 wB2 = *(const ulonglong2*)&WsT[32 + c][dbase + 8];
        ulonglong2 wB3 = *(const ulonglong2*)&WsT[32 + c][dbase + 12];
        u64 w1[8] = {wA0.x, wA0.y, wA1.x, wA1.y, wA2.x, wA2.y, wA3.x, wA3.y};
        u64 w2[8] = {wB0.x, wB0.y, wB1.x, wB1.y, wB2.x, wB2.y, wB3.x, wB3.y};
        #pragma unroll
        for (int k = 0; k < 8; k++) {
            #pragma unroll
            for (int p = 0; p < 4; p++) {
                acc[p][k] = fma2(ax[p], w1[k], acc[p][k]);
                acc[p][k] = fma2(bx[p], w2[k], acc[p][k]);
            }
        }
    }

    #pragma unroll
    for (int p = 0; p < 4; p++) {
        float* o = out + (size_t)(p0 + pg * 4 + p) * 64 + dbase;
        #pragma unroll
        for (int k = 0; k < 4; k++) {
            float2 lo = unpk(acc[p][2 * k]);
            float2 hi = unpk(acc[p][2 * k + 1]);
            *(float4*)&o[4 * k] = make_float4(lo.x, lo.y, hi.x, hi.y);
        }
    }
}

// ---------------- launch ----------------
extern "C" void kernel_launch(void* const* d_in, const int* in_sizes, int n_in,
                              void* d_out, int out_size)
{
    const float* x      = (const float*)d_in[0];
    const float* w_qkv  = (const float*)d_in[1];
    const float* b_qkv  = (const float*)d_in[2];
    const float* pos    = (const float*)d_in[3];
    const float* amp_w  = (const float*)d_in[4];
    const float* amp_b  = (const float*)d_in[5];
    const float* pha_w  = (const float*)d_in[6];
    const float* pha_b  = (const float*)d_in[7];
    const float* proj_w = (const float*)d_in[8];
    const float* proj_b = (const float*)d_in[9];
    float* out = (float*)d_out;

    transpose_pos_kernel<<<64, 256>>>(pos);
    attn_kernel<<<8192, 256>>>(x, w_qkv, b_qkv);
    rowfft_kernel<<<4096, 256>>>(x);
    coltrans_kernel<<<dim3(17, 256), 256>>>(amp_w, amp_b, pha_w, pha_b);
    rowifft_kernel<<<4096, 256>>>();
    proj_kernel<<<8192, 64>>>(proj_w, proj_b, out);
}

// round 11
// speedup vs baseline: 1.0790x; 1.0368x over previous
#include <cuda_runtime.h>
#include <cstdint>

#define PI_F 3.14159265358979323846f
typedef unsigned long long u64;

// ---------------- scratch (device globals; no runtime allocation) ----------------
__device__ float2 g_spec[256u * 256u * 129u];      // [img=b*32+ch][row][k] spectrum
__device__ float  g_x1[8u * 256u * 256u * 32u];    // [pix][32] local-mixer out
__device__ float  g_x2[256u * 256u * 256u];        // [img][row][w] global-mixer out
__device__ float  g_posT[4 * 64 * 64];             // pos transposed: [h][j][i]

// ---------------- packed f32x2 helpers ----------------
__device__ __forceinline__ u64 fma2(u64 a, u64 b, u64 c) {
    u64 d; asm("fma.rn.f32x2 %0, %1, %2, %3;" : "=l"(d) : "l"(a), "l"(b), "l"(c)); return d;
}
__device__ __forceinline__ u64 add2(u64 a, u64 b) {
    u64 d; asm("add.rn.f32x2 %0, %1, %2;" : "=l"(d) : "l"(a), "l"(b)); return d;
}
__device__ __forceinline__ u64 mul2(u64 a, u64 b) {
    u64 d; asm("mul.rn.f32x2 %0, %1, %2;" : "=l"(d) : "l"(a), "l"(b)); return d;
}
__device__ __forceinline__ u64 pack2(float lo, float hi) {
    u64 r; asm("mov.b64 %0, {%1, %2};" : "=l"(r) : "f"(lo), "f"(hi)); return r;
}
__device__ __forceinline__ float2 unpk(u64 v) {
    float2 r; asm("mov.b64 {%0, %1}, %2;" : "=f"(r.x), "=f"(r.y) : "l"(v)); return r;
}
__device__ __forceinline__ u64 swap2(u64 a) {      // (x,y) -> (y,x); register renames
    float2 f = unpk(a); return pack2(f.y, f.x);
}
__device__ __forceinline__ float2 cmulf(float2 a, float2 b) {
    return make_float2(a.x * b.x - a.y * b.y, a.x * b.y + a.y * b.x);
}
// complex a * (c + i s), packed: c2 = (c,c), s2m = (-s, s)
__device__ __forceinline__ u64 rotu(u64 a, u64 c2, u64 s2m) {
    return fma2(swap2(a), s2m, mul2(a, c2));
}
__device__ __forceinline__ int rev5(int l) {
    return ((l & 1) << 4) | ((l & 2) << 2) | (l & 4) | ((l & 8) >> 2) | ((l & 16) >> 4);
}
// smem index maps (conflict-free by construction)
__device__ __forceinline__ int zin(int n, int f) { return n ^ (4 * f); }            // natural staging
__device__ __forceinline__ int zq(int q, int p)  { return q * 32 + (p ^ (4 * q)); } // spectral (q,p)
__device__ __forceinline__ int zpos(int k)       { return zq(k & 7, k >> 3); }      // spectral by k

// ---------------- warp-level 256-pt FFT, packed f32x2, branchless ----------------
template <int SIGN>
__device__ __forceinline__ void reg_fft8_dif(u64 v[8], u64 neg1) {
    const float S = (float)SIGN;
    const float C = 0.70710678118654752f;
    u64 cC  = pack2(C, C);
    u64 cCn = pack2(-C, -C);
    u64 sSC = pack2(-S * C, S * C);
    u64 iS  = pack2(-S, S);
    {
        u64 t0 = fma2(v[4], neg1, v[0]);
        u64 t1 = fma2(v[5], neg1, v[1]);
        u64 t2 = fma2(v[6], neg1, v[2]);
        u64 t3 = fma2(v[7], neg1, v[3]);
        v[0] = add2(v[0], v[4]); v[1] = add2(v[1], v[5]);
        v[2] = add2(v[2], v[6]); v[3] = add2(v[3], v[7]);
        v[4] = t0;
        v[5] = rotu(t1, cC, sSC);
        v[6] = mul2(swap2(t2), iS);
        v[7] = rotu(t3, cCn, sSC);
    }
    #pragma unroll
    for (int b = 0; b < 8; b += 4) {
        u64 u0 = fma2(v[b + 2], neg1, v[b]);
        u64 u1 = fma2(v[b + 3], neg1, v[b + 1]);
        v[b]     = add2(v[b], v[b + 2]);
        v[b + 1] = add2(v[b + 1], v[b + 3]);
        v[b + 2] = u0;
        v[b + 3] = mul2(swap2(u1), iS);
    }
    #pragma unroll
    for (int b = 0; b < 8; b += 2) {
        u64 a = v[b], c = v[b + 1];
        v[b] = add2(a, c);
        v[b + 1] = fma2(c, neg1, a);
    }
}

template <int SIGN>
__device__ __forceinline__ void reg_fft8_dit(u64 v[8], u64 neg1) {
    const float S = (float)SIGN;
    const float C = 0.70710678118654752f;
    u64 cC  = pack2(C, C);
    u64 cCn = pack2(-C, -C);
    u64 sSC = pack2(-S * C, S * C);
    u64 iS  = pack2(-S, S);
    #pragma unroll
    for (int b = 0; b < 8; b += 2) {
        u64 a = v[b], c = v[b + 1];
        v[b] = add2(a, c);
        v[b + 1] = fma2(c, neg1, a);
    }
    #pragma unroll
    for (int b = 0; b < 8; b += 4) {
        u64 t0 = v[b + 2];
        u64 t1 = mul2(swap2(v[b + 3]), iS);
        u64 a0 = v[b], a1 = v[b + 1];
        v[b]     = add2(a0, t0); v[b + 2] = fma2(t0, neg1, a0);
        v[b + 1] = add2(a1, t1); v[b + 3] = fma2(t1, neg1, a1);
    }
    {
        u64 t0 = v[4];
        u64 t1 = rotu(v[5], cC, sSC);
        u64 t2 = mul2(swap2(v[6]), iS);
        u64 t3 = rotu(v[7], cCn, sSC);
        u64 a0 = v[0], a1 = v[1], a2 = v[2], a3 = v[3];
        v[0] = add2(a0, t0); v[4] = fma2(t0, neg1, a0);
        v[1] = add2(a1, t1); v[5] = fma2(t1, neg1, a1);
        v[2] = add2(a2, t2); v[6] = fma2(t2, neg1, a2);
        v[3] = add2(a3, t3); v[7] = fma2(t3, neg1, a3);
    }
}

template <int SIGN>
__device__ __forceinline__ void mid_twiddle(u64 v[8], int lane) {
    float ang = (float)SIGN * (2.0f * PI_F / 256.0f) * (float)lane;
    float sn, cs; __sincosf(ang, &sn, &cs);
    float2 w1 = make_float2(cs, sn);
    float2 w2 = cmulf(w1, w1);
    float2 w3 = cmulf(w2, w1);
    float2 w4 = cmulf(w2, w2);
    float2 w5 = cmulf(w4, w1);
    float2 w6 = cmulf(w4, w2);
    float2 w7 = cmulf(w4, w3);
    v[1] = rotu(v[1], pack2(w4.x, w4.x), pack2(-w4.y, w4.y));
    v[2] = rotu(v[2], pack2(w2.x, w2.x), pack2(-w2.y, w2.y));
    v[3] = rotu(v[3], pack2(w6.x, w6.x), pack2(-w6.y, w6.y));
    v[4] = rotu(v[4], pack2(w1.x, w1.x), pack2(-w1.y, w1.y));
    v[5] = rotu(v[5], pack2(w5.x, w5.x), pack2(-w5.y, w5.y));
    v[6] = rotu(v[6], pack2(w3.x, w3.x), pack2(-w3.y, w3.y));
    v[7] = rotu(v[7], pack2(w7.x, w7.x), pack2(-w7.y, w7.y));
}

template <int SIGN>
__device__ __forceinline__ void lane_fft_dif(u64 v[8], int lane) {
    #pragma unroll
    for (int h = 16; h >= 1; h >>= 1) {
        int j = lane & (h - 1);
        float ang = (float)SIGN * (2.0f * PI_F / 32.0f) * (float)(j * (16 / h));
        float sn, cs; __sincosf(ang, &sn, &cs);
        bool up = (lane & h) != 0;
        float twc = up ? cs : 1.0f;
        float tws = up ? sn : 0.0f;
        float sg  = up ? -1.0f : 1.0f;
        u64 sg2 = pack2(sg, sg);
        u64 c2  = pack2(twc, twc);
        u64 s2m = pack2(-tws, tws);
        #pragma unroll
        for (int r = 0; r < 8; r++) {
            float2 f = unpk(v[r]);
            float ox = __shfl_xor_sync(0xffffffffu, f.x, h);
            float oy = __shfl_xor_sync(0xffffffffu, f.y, h);
            u64 u = fma2(sg2, v[r], pack2(ox, oy));   // lower: v+o ; upper: o−v
            v[r] = rotu(u, c2, s2m);                  // lower twiddle = (1,0)
        }
    }
}

template <int SIGN>
__device__ __forceinline__ void lane_fft_dit(u64 v[8], int lane) {
    #pragma unroll
    for (int d = 1; d <= 16; d <<= 1) {
        int j = lane & (d - 1);
        float ang = (float)SIGN * (2.0f * PI_F / 32.0f) * (float)(j * (16 / d));
        float sn, cs; __sincosf(ang, &sn, &cs);
        bool up = (lane & d) != 0;
        float twc = up ? cs : 1.0f;
        float tws = up ? sn : 0.0f;
        float sg  = up ? -1.0f : 1.0f;
        u64 sg2 = pack2(sg, sg);
        u64 c2  = pack2(twc, twc);
        u64 s2m = pack2(-tws, tws);
        #pragma unroll
        for (int r = 0; r < 8; r++) {
            u64 rv = rotu(v[r], c2, s2m);             // identity on lower lanes
            float2 f = unpk(rv);
            float ox = __shfl_xor_sync(0xffffffffu, f.x, d);
            float oy = __shfl_xor_sync(0xffffffffu, f.y, d);
            v[r] = fma2(sg2, rv, pack2(ox, oy));      // lower: rv+o ; upper: o−rv
        }
    }
}

__device__ __forceinline__ void warp_fft256_fwd(u64 v[8], int lane, u64 neg1) {
    reg_fft8_dif<-1>(v, neg1);
    mid_twiddle<-1>(v, lane);
    lane_fft_dif<-1>(v, lane);
}
__device__ __forceinline__ void warp_fft256_inv(u64 v[8], int lane, u64 neg1) {
    lane_fft_dit<1>(v, lane);
    mid_twiddle<1>(v, lane);
    reg_fft8_dit<1>(v, neg1);
}

// ---------------- pos transpose (tiny, once per launch) ----------------
__global__ __launch_bounds__(256) void transpose_pos_kernel(const float* __restrict__ pos)
{
    int idx = blockIdx.x * 256 + threadIdx.x;
    int h = idx >> 12;
    int j = (idx >> 6) & 63;
    int i = idx & 63;
    g_posT[idx] = pos[((h * 64) + i) * 64 + j];
}

// ---------------- local mixer: window attention ----------------
// single-pass softmax (inputs bounded -> exp without max shift is safe in fp32)
__global__ __launch_bounds__(256) void attn_kernel(
    const float* __restrict__ x, const float* __restrict__ wqkv,
    const float* __restrict__ bqkv)
{
    __shared__ float xw[64][36];
    __shared__ float wq[96][36];
    __shared__ float bq[96];
    __shared__ float ks[64][36];
    __shared__ float vs[64][36];

    int t = threadIdx.x;
    int wid = blockIdx.x;
    int b   = wid >> 10;
    int hb  = (wid >> 5) & 31;
    int wb  = wid & 31;

    {
        const float4* xv = (const float4*)x;
        #pragma unroll
        for (int e = 0; e < 2; e++) {
            int l = t + e * 256;
            int n = l >> 3;
            int q4 = l & 7;
            int i = n >> 3, j = n & 7;
            size_t pix = ((size_t)(b * 256 + hb * 8 + i) * 256) + (wb * 8 + j);
            *(float4*)&xw[n][q4 * 4] = xv[pix * 16 + q4];
        }
        #pragma unroll
        for (int e = 0; e < 12; e++) {
            int l = t + e * 256;
            wq[l >> 5][l & 31] = wqkv[l];
        }
        if (t < 96) bq[t] = bqkv[t];
    }
    __syncthreads();

    int i  = t & 63;
    int hq = t >> 6;

    u64 xr[16];
    #pragma unroll
    for (int c = 0; c < 8; c++) {
        ulonglong2 v = *(const ulonglong2*)&xw[i][4 * c];
        xr[2 * c] = v.x; xr[2 * c + 1] = v.y;
    }

    u64 q2[4];
    #pragma unroll
    for (int kind = 0; kind < 3; kind++) {
        float o[8];
        #pragma unroll
        for (int dd = 0; dd < 8; dd++) {
            int d = kind * 32 + hq * 8 + dd;
            const float* wrow = &wq[d][0];
            u64 a0 = 0ull, a1 = 0ull;
            #pragma unroll
            for (int c = 0; c < 4; c++) {
                ulonglong2 w0 = *(const ulonglong2*)(wrow + 8 * c);
                ulonglong2 w1 = *(const ulonglong2*)(wrow + 8 * c + 4);
                a0 = fma2(xr[4 * c],     w0.x, a0);
                a1 = fma2(xr[4 * c + 1], w0.y, a1);
                a0 = fma2(xr[4 * c + 2], w1.x, a0);
                a1 = fma2(xr[4 * c + 3], w1.y, a1);
            }
            float2 p = unpk(a0), q = unpk(a1);
            o[dd] = p.x + p.y + q.x + q.y + bq[d];
        }
        if (kind == 0) {
            #pragma unroll
            for (int c = 0; c < 4; c++)
                q2[c] = pack2(o[2 * c]     * 0.35355339059327373f,
                              o[2 * c + 1] * 0.35355339059327373f);
        } else if (kind == 1) {
            *(float4*)&ks[i][hq * 8]     = make_float4(o[0], o[1], o[2], o[3]);
            *(float4*)&ks[i][hq * 8 + 4] = make_float4(o[4], o[5], o[6], o[7]);
        } else {
            *(float4*)&vs[i][hq * 8]     = make_float4(o[0], o[1], o[2], o[3]);
            *(float4*)&vs[i][hq * 8 + 4] = make_float4(o[4], o[5], o[6], o[7]);
        }
    }
    __syncthreads();

    // fused attention pass: thread = (head hq, query row i). K/V rows uniform per warp.
    {
        const float* pT = g_posT + hq * 4096 + i;   // pT[j*64] coalesced across lanes
        float sum = 0.f;
        u64 o2[4] = {0ull, 0ull, 0ull, 0ull};
        #pragma unroll
        for (int j = 0; j < 64; j++) {
            ulonglong2 k0 = *(const ulonglong2*)&ks[j][hq * 8];
            ulonglong2 k1 = *(const ulonglong2*)&ks[j][hq * 8 + 4];
            u64 a = 0ull;
            a = fma2(q2[0], k0.x, a);
            a = fma2(q2[1], k0.y, a);
            a = fma2(q2[2], k1.x, a);
            a = fma2(q2[3], k1.y, a);
            float2 p = unpk(a);
            float s = p.x + p.y + pT[j * 64];
            float e = __expf(s);          // bounded inputs: no max shift needed
            sum += e;
            ulonglong2 v0 = *(const ulonglong2*)&vs[j][hq * 8];
            ulonglong2 v1 = *(const ulonglong2*)&vs[j][hq * 8 + 4];
            u64 pb = pack2(e, e);
            o2[0] = fma2(pb, v0.x, o2[0]);
            o2[1] = fma2(pb, v0.y, o2[1]);
            o2[2] = fma2(pb, v1.x, o2[2]);
            o2[3] = fma2(pb, v1.y, o2[3]);
        }
        float inv = 1.f / sum;
        float2 r0 = unpk(o2[0]), r1 = unpk(o2[1]), r2 = unpk(o2[2]), r3 = unpk(o2[3]);
        int ir = i >> 3, jc = i & 7;
        size_t pix = ((size_t)(b * 256 + hb * 8 + ir) * 256) + (wb * 8 + jc);
        float4* op = (float4*)(g_x1 + pix * 32 + hq * 8);
        op[0] = make_float4(r0.x * inv, r0.y * inv, r1.x * inv, r1.y * inv);
        op[1] = make_float4(r2.x * inv, r2.y * inv, r3.x * inv, r3.y * inv);
    }
}

// ---------------- forward row rFFT, 2 real channels per complex warp-FFT --------
__global__ __launch_bounds__(256, 4) void rowfft_kernel(const float* __restrict__ x)
{
    __shared__ float2 sbuf[8 * 256];
    u64* sb = (u64*)sbuf;
    int t  = threadIdx.x;
    int lane = t & 31, w = t >> 5;
    int bx = blockIdx.x;
    int b   = bx >> 9;
    int row = (bx >> 1) & 255;
    int g   = bx & 1;
    u64 neg1 = pack2(-1.f, -1.f);

    const float* xp = x + ((size_t)(b * 256 + row) * 256) * 64 + 32 + g * 16;
    #pragma unroll
    for (int e = 0; e < 8; e++) {
        int l = t + e * 256;
        int n = l >> 3;
        int f = l & 7;
        sb[f * 256 + zin(n, f)] = *(const u64*)(xp + (size_t)n * 64 + 2 * f);
    }
    __syncthreads();

    u64 v[8];
    #pragma unroll
    for (int m2 = 0; m2 < 8; m2++) v[m2] = sb[w * 256 + zin(lane + 32 * m2, w)];
    warp_fft256_fwd(v, lane, neg1);

    int p = rev5(lane);
    const int Q[8] = {0, 4, 2, 6, 1, 5, 3, 7};
    #pragma unroll
    for (int r = 0; r < 8; r++) sb[w * 256 + zq(Q[r], p)] = v[r];
    __syncthreads();

    int img0 = b * 32 + g * 16;
    if (t < 129) {
        int m = (256 - t) & 255;
        int pt = zpos(t), pm = zpos(m);
        #pragma unroll
        for (int f = 0; f < 8; f++) {
            float2 zk = sbuf[f * 256 + pt];
            float2 zm = sbuf[f * 256 + pm];
            float2 A  = make_float2(0.5f * (zk.x + zm.x), 0.5f * (zk.y - zm.y));
            float2 Bv = make_float2(0.5f * (zk.y + zm.y), 0.5f * (zm.x - zk.x));
            size_t o = ((size_t)(img0 + 2 * f) * 256 + row) * 129 + t;
            g_spec[o] = A;
            g_spec[o + (size_t)256 * 129] = Bv;
        }
    }
}

// ---------------- column FFT + amp/phase transform + column IFFT ---------------
__global__ __launch_bounds__(256, 4) void coltrans_kernel(
    const float* __restrict__ amp_w, const float* __restrict__ amp_b,
    const float* __restrict__ pha_w, const float* __restrict__ pha_b)
{
    __shared__ float2 sbuf[8 * 256];
    u64* sb = (u64*)sbuf;
    int t   = threadIdx.x;
    int lane = t & 31, w = t >> 5;
    int img = blockIdx.y;
    int k0  = blockIdx.x * 8;
    int ch  = img & 31;
    u64 neg1 = pack2(-1.f, -1.f);

    float aw = amp_w[ch], ab = amp_b[ch], pw = pha_w[ch], pb = pha_b[ch];

    size_t base = (size_t)img * 256 * 129;
    #pragma unroll
    for (int e = 0; e < 8; e++) {
        int l = t + e * 256;
        int row = l >> 3;
        int kk  = l & 7;
        int k   = k0 + kk;
        float2 vv = make_float2(0.f, 0.f);
        if (k < 129) vv = g_spec[base + (size_t)row * 129 + k];
        sbuf[kk * 256 + zin(row, kk)] = vv;
    }
    __syncthreads();

    u64 v[8];
    #pragma unroll
    for (int m2 = 0; m2 < 8; m2++) v[m2] = sb[w * 256 + zin(lane + 32 * m2, w)];
    warp_fft256_fwd(v, lane, neg1);

    #pragma unroll
    for (int m2 = 0; m2 < 8; m2++) {
        float2 vv = unpk(v[m2]);
        float amp = sqrtf(vv.x * vv.x + vv.y * vv.y);
        float pha = atan2f(vv.y, vv.x);
        float af = amp * aw + ab;
        float pf = pha * pw + pb;
        float sn, cs; __sincosf(pf, &sn, &cs);
        v[m2] = pack2(af * cs + 2e-8f, af * sn + 1e-8f);
    }

    warp_fft256_inv(v, lane, neg1);
    #pragma unroll
    for (int m2 = 0; m2 < 8; m2++) sb[w * 256 + zin(lane + 32 * m2, w)] = v[m2];
    __syncthreads();

    #pragma unroll
    for (int e = 0; e < 8; e++) {
        int l = t + e * 256;
        int row = l >> 3;
        int kk  = l & 7;
        int k   = k0 + kk;
        if (k < 129) g_spec[base + (size_t)row * 129 + k] = sbuf[kk * 256 + zin(row, kk)];
    }
}

// ---------------- inverse row irFFT + abs, 2 image planes per warp-FFT ----------
__global__ __launch_bounds__(256, 4) void rowifft_kernel()
{
    __shared__ float2 sbuf[8 * 256];
    u64* sb = (u64*)sbuf;
    int t  = threadIdx.x;
    int lane = t & 31, w = t >> 5;
    int bx = blockIdx.x;
    int pr   = bx >> 5;
    int row0 = (bx & 31) * 8;
    int imgA = 2 * pr;
    u64 neg1 = pack2(-1.f, -1.f);

    size_t baseA = ((size_t)imgA * 256 + row0) * 129;
    size_t baseB = baseA + (size_t)256 * 129;
    if (t < 129) {
        bool edge = (t == 0) || (t == 128);
        int pt = zpos(t), pm = zpos((256 - t) & 255);
        #pragma unroll
        for (int f = 0; f < 8; f++) {
            float2 A  = g_spec[baseA + (size_t)f * 129 + t];
            float2 Bv = g_spec[baseB + (size_t)f * 129 + t];
            if (edge) { A.y = 0.f; Bv.y = 0.f; }   // irfft discards Im at DC/Nyquist
            sbuf[f * 256 + pt] = make_float2(A.x - Bv.y, A.y + Bv.x);
            if (t >= 1 && t < 128)
                sbuf[f * 256 + pm] = make_float2(A.x + Bv.y, Bv.x - A.y);
        }
    }
    __syncthreads();

    u64 v[8];
    int p = rev5(lane);
    const int Q[8] = {0, 4, 2, 6, 1, 5, 3, 7};
    #pragma unroll
    for (int r = 0; r < 8; r++) v[r] = sb[w * 256 + zq(Q[r], p)];
    warp_fft256_inv(v, lane, neg1);

    size_t oA = ((size_t)imgA * 256 + row0 + w) * 256;
    #pragma unroll
    for (int m2 = 0; m2 < 8; m2++) {
        int n = lane + 32 * m2;
        float2 f = unpk(v[m2]);
        g_x2[oA + n]         = fabsf(f.x * (1.f / 65536.f));
        g_x2[oA + 65536 + n] = fabsf(f.y * (1.f / 65536.f));
    }
}

// ---------------- projection (unchanged, working) ----------------
__global__ __launch_bounds__(64) void proj_kernel(
    const float* __restrict__ pw, const float* __restrict__ pbias,
    float* __restrict__ out)
{
    __shared__ float WsT[64][68];
    __shared__ float x1s[32][68];
    __shared__ float x2s[32][68];
    int t  = threadIdx.x;
    int p0 = blockIdx.x * 64;
    int b    = p0 >> 16;
    int rem0 = p0 & 65535;

    #pragma unroll
    for (int e = 0; e < 64; e++) WsT[t][e] = pw[e * 64 + t];
    #pragma unroll
    for (int e = 0; e < 32; e++) {
        int l = e * 64 + t;
        x1s[l & 31][l >> 5] = g_x1[(size_t)p0 * 32 + l];
    }
    {
        size_t xb = (size_t)b * 2097152 + rem0;
        #pragma unroll
        for (int e = 0; e < 32; e++)
            x2s[e][t] = g_x2[xb + (size_t)e * 65536 + t];
    }
    __syncthreads();

    int pg    = t >> 2;
    int dbase = (t & 3) << 4;
    u64 acc[4][8];
    #pragma unroll
    for (int k = 0; k < 8; k++) {
        u64 bp = *(const u64*)&pbias[dbase + 2 * k];
        #pragma unroll
        for (int p = 0; p < 4; p++) acc[p][k] = bp;
    }

    #pragma unroll
    for (int c = 0; c < 32; c++) {
        float4 a  = *(const float4*)&x1s[c][pg * 4];
        float4 b2 = *(const float4*)&x2s[c][pg * 4];
        u64 ax[4] = {pack2(a.x, a.x),   pack2(a.y, a.y),   pack2(a.z, a.z),   pack2(a.w, a.w)};
        u64 bx[4] = {pack2(b2.x, b2.x), pack2(b2.y, b2.y), pack2(b2.z, b2.z), pack2(b2.w, b2.w)};
        ulonglong2 wA0 = *(const ulonglong2*)&WsT[c][dbase];
        ulonglong2 wA1 = *(const ulonglong2*)&WsT[c][dbase + 4];
        ulonglong2 wA2 = *(const ulonglong2*)&WsT[c][dbase + 8];
        ulonglong2 wA3 = *(const ulonglong2*)&WsT[c][dbase + 12];
        ulonglong2 wB0 = *(const ulonglong2*)&WsT[32 + c][dbase];
        ulonglong2 wB1 = *(const ulonglong2*)&WsT[32 + c][dbase + 4];
        ulonglong2 wB2 = *(const ulonglong2*)&WsT[32 + c][dbase + 8];
        ulonglong2 wB3 = *(const ulonglong2*)&WsT[32 + c][dbase + 12];
        u64 w1[8] = {wA0.x, wA0.y, wA1.x, wA1.y, wA2.x, wA2.y, wA3.x, wA3.y};
        u64 w2[8] = {wB0.x, wB0.y, wB1.x, wB1.y, wB2.x, wB2.y, wB3.x, wB3.y};
        #pragma unroll
        for (int k = 0; k < 8; k++) {
            #pragma unroll
            for (int p = 0; p < 4; p++) {
                acc[p][k] = fma2(ax[p], w1[k], acc[p][k]);
                acc[p][k] = fma2(bx[p], w2[k], acc[p][k]);
            }
        }
    }

    #pragma unroll
    for (int p = 0; p < 4; p++) {
        float* o = out + (size_t)(p0 + pg * 4 + p) * 64 + dbase;
        #pragma unroll
        for (int k = 0; k < 4; k++) {
            float2 lo = unpk(acc[p][2 * k]);
            float2 hi = unpk(acc[p][2 * k + 1]);
            *(float4*)&o[4 * k] = make_float4(lo.x, lo.y, hi.x, hi.y);
        }
    }
}

// ---------------- launch (reordered: attn at profiled slot #3) ----------------
extern "C" void kernel_launch(void* const* d_in, const int* in_sizes, int n_in,
                              void* d_out, int out_size)
{
    const float* x      = (const float*)d_in[0];
    const float* w_qkv  = (const float*)d_in[1];
    const float* b_qkv  = (const float*)d_in[2];
    const float* pos    = (const float*)d_in[3];
    const float* amp_w  = (const float*)d_in[4];
    const float* amp_b  = (const float*)d_in[5];
    const float* pha_w  = (const float*)d_in[6];
    const float* pha_b  = (const float*)d_in[7];
    const float* proj_w = (const float*)d_in[8];
    const float* proj_b = (const float*)d_in[9];
    float* out = (float*)d_out;

    transpose_pos_kernel<<<64, 256>>>(pos);
    rowfft_kernel<<<4096, 256>>>(x);
    coltrans_kernel<<<dim3(17, 256), 256>>>(amp_w, amp_b, pha_w, pha_b);
    attn_kernel<<<8192, 256>>>(x, w_qkv, b_qkv);
    rowifft_kernel<<<4096, 256>>>();
    proj_kernel<<<8192, 64>>>(proj_w, proj_b, out);
}

// round 12
// speedup vs baseline: 1.1328x; 1.0499x over previous
#include <cuda_runtime.h>
#include <cstdint>

#define PI_F 3.14159265358979323846f
typedef unsigned long long u64;

// ---------------- scratch (device globals; no runtime allocation) ----------------
__device__ float2 g_spec[256u * 256u * 129u];      // [img=b*32+ch][row][k] spectrum
__device__ float  g_x1[8u * 256u * 256u * 32u];    // [pix][32] local-mixer out
__device__ float  g_x2[256u * 256u * 256u];        // [img][row][w] global-mixer out
__device__ float  g_posT[4 * 64 * 64];             // pos transposed: [h][j][i]

// ---------------- packed f32x2 helpers ----------------
__device__ __forceinline__ u64 fma2(u64 a, u64 b, u64 c) {
    u64 d; asm("fma.rn.f32x2 %0, %1, %2, %3;" : "=l"(d) : "l"(a), "l"(b), "l"(c)); return d;
}
__device__ __forceinline__ u64 add2(u64 a, u64 b) {
    u64 d; asm("add.rn.f32x2 %0, %1, %2;" : "=l"(d) : "l"(a), "l"(b)); return d;
}
__device__ __forceinline__ u64 mul2(u64 a, u64 b) {
    u64 d; asm("mul.rn.f32x2 %0, %1, %2;" : "=l"(d) : "l"(a), "l"(b)); return d;
}
__device__ __forceinline__ u64 pack2(float lo, float hi) {
    u64 r; asm("mov.b64 %0, {%1, %2};" : "=l"(r) : "f"(lo), "f"(hi)); return r;
}
__device__ __forceinline__ float2 unpk(u64 v) {
    float2 r; asm("mov.b64 {%0, %1}, %2;" : "=f"(r.x), "=f"(r.y) : "l"(v)); return r;
}
__device__ __forceinline__ u64 swap2(u64 a) {      // (x,y) -> (y,x); register renames
    float2 f = unpk(a); return pack2(f.y, f.x);
}
__device__ __forceinline__ float2 cmulf(float2 a, float2 b) {
    return make_float2(a.x * b.x - a.y * b.y, a.x * b.y + a.y * b.x);
}
// complex a * (c + i s), packed: c2 = (c,c), s2m = (-s, s)
__device__ __forceinline__ u64 rotu(u64 a, u64 c2, u64 s2m) {
    return fma2(swap2(a), s2m, mul2(a, c2));
}
__device__ __forceinline__ int rev5(int l) {
    return ((l & 1) << 4) | ((l & 2) << 2) | (l & 4) | ((l & 8) >> 2) | ((l & 16) >> 4);
}
// smem index maps (conflict-free by construction)
__device__ __forceinline__ int zin(int n, int f) { return n ^ (4 * f); }            // natural staging
__device__ __forceinline__ int zq(int q, int p)  { return q * 32 + (p ^ (4 * q)); } // spectral (q,p)
__device__ __forceinline__ int zpos(int k)       { return zq(k & 7, k >> 3); }      // spectral by k

// ---------------- warp-level 256-pt FFT, packed f32x2, branchless ----------------
template <int SIGN>
__device__ __forceinline__ void reg_fft8_dif(u64 v[8], u64 neg1) {
    const float S = (float)SIGN;
    const float C = 0.70710678118654752f;
    u64 cC  = pack2(C, C);
    u64 cCn = pack2(-C, -C);
    u64 sSC = pack2(-S * C, S * C);
    u64 iS  = pack2(-S, S);
    {
        u64 t0 = fma2(v[4], neg1, v[0]);
        u64 t1 = fma2(v[5], neg1, v[1]);
        u64 t2 = fma2(v[6], neg1, v[2]);
        u64 t3 = fma2(v[7], neg1, v[3]);
        v[0] = add2(v[0], v[4]); v[1] = add2(v[1], v[5]);
        v[2] = add2(v[2], v[6]); v[3] = add2(v[3], v[7]);
        v[4] = t0;
        v[5] = rotu(t1, cC, sSC);
        v[6] = mul2(swap2(t2), iS);
        v[7] = rotu(t3, cCn, sSC);
    }
    #pragma unroll
    for (int b = 0; b < 8; b += 4) {
        u64 u0 = fma2(v[b + 2], neg1, v[b]);
        u64 u1 = fma2(v[b + 3], neg1, v[b + 1]);
        v[b]     = add2(v[b], v[b + 2]);
        v[b + 1] = add2(v[b + 1], v[b + 3]);
        v[b + 2] = u0;
        v[b + 3] = mul2(swap2(u1), iS);
    }
    #pragma unroll
    for (int b = 0; b < 8; b += 2) {
        u64 a = v[b], c = v[b + 1];
        v[b] = add2(a, c);
        v[b + 1] = fma2(c, neg1, a);
    }
}

template <int SIGN>
__device__ __forceinline__ void reg_fft8_dit(u64 v[8], u64 neg1) {
    const float S = (float)SIGN;
    const float C = 0.70710678118654752f;
    u64 cC  = pack2(C, C);
    u64 cCn = pack2(-C, -C);
    u64 sSC = pack2(-S * C, S * C);
    u64 iS  = pack2(-S, S);
    #pragma unroll
    for (int b = 0; b < 8; b += 2) {
        u64 a = v[b], c = v[b + 1];
        v[b] = add2(a, c);
        v[b + 1] = fma2(c, neg1, a);
    }
    #pragma unroll
    for (int b = 0; b < 8; b += 4) {
        u64 t0 = v[b + 2];
        u64 t1 = mul2(swap2(v[b + 3]), iS);
        u64 a0 = v[b], a1 = v[b + 1];
        v[b]     = add2(a0, t0); v[b + 2] = fma2(t0, neg1, a0);
        v[b + 1] = add2(a1, t1); v[b + 3] = fma2(t1, neg1, a1);
    }
    {
        u64 t0 = v[4];
        u64 t1 = rotu(v[5], cC, sSC);
        u64 t2 = mul2(swap2(v[6]), iS);
        u64 t3 = rotu(v[7], cCn, sSC);
        u64 a0 = v[0], a1 = v[1], a2 = v[2], a3 = v[3];
        v[0] = add2(a0, t0); v[4] = fma2(t0, neg1, a0);
        v[1] = add2(a1, t1); v[5] = fma2(t1, neg1, a1);
        v[2] = add2(a2, t2); v[6] = fma2(t2, neg1, a2);
        v[3] = add2(a3, t3); v[7] = fma2(t3, neg1, a3);
    }
}

template <int SIGN>
__device__ __forceinline__ void mid_twiddle(u64 v[8], int lane) {
    float ang = (float)SIGN * (2.0f * PI_F / 256.0f) * (float)lane;
    float sn, cs; __sincosf(ang, &sn, &cs);
    float2 w1 = make_float2(cs, sn);
    float2 w2 = cmulf(w1, w1);
    float2 w3 = cmulf(w2, w1);
    float2 w4 = cmulf(w2, w2);
    float2 w5 = cmulf(w4, w1);
    float2 w6 = cmulf(w4, w2);
    float2 w7 = cmulf(w4, w3);
    v[1] = rotu(v[1], pack2(w4.x, w4.x), pack2(-w4.y, w4.y));
    v[2] = rotu(v[2], pack2(w2.x, w2.x), pack2(-w2.y, w2.y));
    v[3] = rotu(v[3], pack2(w6.x, w6.x), pack2(-w6.y, w6.y));
    v[4] = rotu(v[4], pack2(w1.x, w1.x), pack2(-w1.y, w1.y));
    v[5] = rotu(v[5], pack2(w5.x, w5.x), pack2(-w5.y, w5.y));
    v[6] = rotu(v[6], pack2(w3.x, w3.x), pack2(-w3.y, w3.y));
    v[7] = rotu(v[7], pack2(w7.x, w7.x), pack2(-w7.y, w7.y));
}

template <int SIGN>
__device__ __forceinline__ void lane_fft_dif(u64 v[8], int lane) {
    #pragma unroll
    for (int h = 16; h >= 1; h >>= 1) {
        int j = lane & (h - 1);
        float ang = (float)SIGN * (2.0f * PI_F / 32.0f) * (float)(j * (16 / h));
        float sn, cs; __sincosf(ang, &sn, &cs);
        bool up = (lane & h) != 0;
        float twc = up ? cs : 1.0f;
        float tws = up ? sn : 0.0f;
        float sg  = up ? -1.0f : 1.0f;
        u64 sg2 = pack2(sg, sg);
        u64 c2  = pack2(twc, twc);
        u64 s2m = pack2(-tws, tws);
        #pragma unroll
        for (int r = 0; r < 8; r++) {
            float2 f = unpk(v[r]);
            float ox = __shfl_xor_sync(0xffffffffu, f.x, h);
            float oy = __shfl_xor_sync(0xffffffffu, f.y, h);
            u64 u = fma2(sg2, v[r], pack2(ox, oy));   // lower: v+o ; upper: o−v
            v[r] = rotu(u, c2, s2m);                  // lower twiddle = (1,0)
        }
    }
}

template <int SIGN>
__device__ __forceinline__ void lane_fft_dit(u64 v[8], int lane) {
    #pragma unroll
    for (int d = 1; d <= 16; d <<= 1) {
        int j = lane & (d - 1);
        float ang = (float)SIGN * (2.0f * PI_F / 32.0f) * (float)(j * (16 / d));
        float sn, cs; __sincosf(ang, &sn, &cs);
        bool up = (lane & d) != 0;
        float twc = up ? cs : 1.0f;
        float tws = up ? sn : 0.0f;
        float sg  = up ? -1.0f : 1.0f;
        u64 sg2 = pack2(sg, sg);
        u64 c2  = pack2(twc, twc);
        u64 s2m = pack2(-tws, tws);
        #pragma unroll
        for (int r = 0; r < 8; r++) {
            u64 rv = rotu(v[r], c2, s2m);             // identity on lower lanes
            float2 f = unpk(rv);
            float ox = __shfl_xor_sync(0xffffffffu, f.x, d);
            float oy = __shfl_xor_sync(0xffffffffu, f.y, d);
            v[r] = fma2(sg2, rv, pack2(ox, oy));      // lower: rv+o ; upper: o−rv
        }
    }
}

__device__ __forceinline__ void warp_fft256_fwd(u64 v[8], int lane, u64 neg1) {
    reg_fft8_dif<-1>(v, neg1);
    mid_twiddle<-1>(v, lane);
    lane_fft_dif<-1>(v, lane);
}
__device__ __forceinline__ void warp_fft256_inv(u64 v[8], int lane, u64 neg1) {
    lane_fft_dit<1>(v, lane);
    mid_twiddle<1>(v, lane);
    reg_fft8_dit<1>(v, neg1);
}

// ---------------- pos transpose (tiny, once per launch) ----------------
__global__ __launch_bounds__(256) void transpose_pos_kernel(const float* __restrict__ pos)
{
    int idx = blockIdx.x * 256 + threadIdx.x;
    int h = idx >> 12;
    int j = (idx >> 6) & 63;
    int i = idx & 63;
    g_posT[idx] = pos[((h * 64) + i) * 64 + j];
}

// ---------------- local mixer: window attention ----------------
// 128 threads/block: thread = (head hq = t>>5, lane), queries lane and lane+32.
// Every warp-uniform broadcast LDS (weights, K, V) now feeds TWO queries.
__global__ __launch_bounds__(128) void attn_kernel(
    const float* __restrict__ x, const float* __restrict__ wqkv,
    const float* __restrict__ bqkv)
{
    __shared__ float xw[64][36];
    __shared__ float wq[96][36];
    __shared__ float bq[96];
    __shared__ float ks[64][36];
    __shared__ float vs[64][36];

    int t = threadIdx.x;            // 0..127
    int lane = t & 31;
    int hq   = t >> 5;              // head
    int wid = blockIdx.x;
    int b   = wid >> 10;
    int hb  = (wid >> 5) & 31;
    int wb  = wid & 31;

    {
        const float4* xv = (const float4*)x;
        #pragma unroll
        for (int e = 0; e < 4; e++) {
            int l = t + e * 128;        // 0..511
            int n = l >> 3;
            int q4 = l & 7;
            int i = n >> 3, j = n & 7;
            size_t pix = ((size_t)(b * 256 + hb * 8 + i) * 256) + (wb * 8 + j);
            *(float4*)&xw[n][q4 * 4] = xv[pix * 16 + q4];
        }
        const float4* wv = (const float4*)wqkv;
        #pragma unroll
        for (int e = 0; e < 6; e++) {
            int l = t + e * 128;        // 0..767 float4s
            *(float4*)&wq[l >> 3][(l & 7) * 4] = wv[l];
        }
        if (t < 96) bq[t] = bqkv[t];
    }
    __syncthreads();

    int i0 = lane, i1 = lane + 32;

    // register-cache BOTH tokens' rows (the LDS-amortization enabler)
    u64 xa[16], xb[16];
    #pragma unroll
    for (int c = 0; c < 8; c++) {
        ulonglong2 va = *(const ulonglong2*)&xw[i0][4 * c];
        ulonglong2 vb = *(const ulonglong2*)&xw[i1][4 * c];
        xa[2 * c] = va.x; xa[2 * c + 1] = va.y;
        xb[2 * c] = vb.x; xb[2 * c + 1] = vb.y;
    }

    u64 q2a[4], q2b[4];
    #pragma unroll
    for (int kind = 0; kind < 3; kind++) {
        float oa[8], ob[8];
        #pragma unroll
        for (int dd = 0; dd < 8; dd++) {
            int d = kind * 32 + hq * 8 + dd;
            const float* wrow = &wq[d][0];
            u64 a0 = 0ull, a1 = 0ull, b0 = 0ull, b1 = 0ull;
            #pragma unroll
            for (int c = 0; c < 4; c++) {
                ulonglong2 w0 = *(const ulonglong2*)(wrow + 8 * c);
                ulonglong2 w1 = *(const ulonglong2*)(wrow + 8 * c + 4);
                a0 = fma2(xa[4 * c],     w0.x, a0);
                a1 = fma2(xa[4 * c + 1], w0.y, a1);
                a0 = fma2(xa[4 * c + 2], w1.x, a0);
                a1 = fma2(xa[4 * c + 3], w1.y, a1);
                b0 = fma2(xb[4 * c],     w0.x, b0);
                b1 = fma2(xb[4 * c + 1], w0.y, b1);
                b0 = fma2(xb[4 * c + 2], w1.x, b0);
                b1 = fma2(xb[4 * c + 3], w1.y, b1);
            }
            float2 pa = unpk(a0), qa = unpk(a1);
            float2 pb = unpk(b0), qb = unpk(b1);
            oa[dd] = pa.x + pa.y + qa.x + qa.y + bq[d];
            ob[dd] = pb.x + pb.y + qb.x + qb.y + bq[d];
        }
        if (kind == 0) {
            #pragma unroll
            for (int c = 0; c < 4; c++) {
                q2a[c] = pack2(oa[2 * c]     * 0.35355339059327373f,
                               oa[2 * c + 1] * 0.35355339059327373f);
                q2b[c] = pack2(ob[2 * c]     * 0.35355339059327373f,
                               ob[2 * c + 1] * 0.35355339059327373f);
            }
        } else if (kind == 1) {
            *(float4*)&ks[i0][hq * 8]     = make_float4(oa[0], oa[1], oa[2], oa[3]);
            *(float4*)&ks[i0][hq * 8 + 4] = make_float4(oa[4], oa[5], oa[6], oa[7]);
            *(float4*)&ks[i1][hq * 8]     = make_float4(ob[0], ob[1], ob[2], ob[3]);
            *(float4*)&ks[i1][hq * 8 + 4] = make_float4(ob[4], ob[5], ob[6], ob[7]);
        } else {
            *(float4*)&vs[i0][hq * 8]     = make_float4(oa[0], oa[1], oa[2], oa[3]);
            *(float4*)&vs[i0][hq * 8 + 4] = make_float4(oa[4], oa[5], oa[6], oa[7]);
            *(float4*)&vs[i1][hq * 8]     = make_float4(ob[0], ob[1], ob[2], ob[3]);
            *(float4*)&vs[i1][hq * 8 + 4] = make_float4(ob[4], ob[5], ob[6], ob[7]);
        }
    }
    __syncthreads();

    // fused attention: single-pass softmax (bounded inputs), 2 queries per thread.
    {
        const float* pT = g_posT + hq * 4096;
        float suma = 0.f, sumb = 0.f;
        u64 oa2[4] = {0ull, 0ull, 0ull, 0ull};
        u64 ob2[4] = {0ull, 0ull, 0ull, 0ull};
        #pragma unroll
        for (int j = 0; j < 64; j++) {
            ulonglong2 k0 = *(const ulonglong2*)&ks[j][hq * 8];
            ulonglong2 k1 = *(const ulonglong2*)&ks[j][hq * 8 + 4];
            u64 aa = 0ull, ab = 0ull;
            aa = fma2(q2a[0], k0.x, aa);  ab = fma2(q2b[0], k0.x, ab);
            aa = fma2(q2a[1], k0.y, aa);  ab = fma2(q2b[1], k0.y, ab);
            aa = fma2(q2a[2], k1.x, aa);  ab = fma2(q2b[2], k1.x, ab);
            aa = fma2(q2a[3], k1.y, aa);  ab = fma2(q2b[3], k1.y, ab);
            float2 fa = unpk(aa), fb = unpk(ab);
            float sa = fa.x + fa.y + pT[j * 64 + i0];
            float sb = fb.x + fb.y + pT[j * 64 + i1];
            float ea = __expf(sa);
            float eb = __expf(sb);
            suma += ea; sumb += eb;
            ulonglong2 v0 = *(const ulonglong2*)&vs[j][hq * 8];
            ulonglong2 v1 = *(const ulonglong2*)&vs[j][hq * 8 + 4];
            u64 pba = pack2(ea, ea), pbb = pack2(eb, eb);
            oa2[0] = fma2(pba, v0.x, oa2[0]);  ob2[0] = fma2(pbb, v0.x, ob2[0]);
            oa2[1] = fma2(pba, v0.y, oa2[1]);  ob2[1] = fma2(pbb, v0.y, ob2[1]);
            oa2[2] = fma2(pba, v1.x, oa2[2]);  ob2[2] = fma2(pbb, v1.x, ob2[2]);
            oa2[3] = fma2(pba, v1.y, oa2[3]);  ob2[3] = fma2(pbb, v1.y, ob2[3]);
        }
        float inva = 1.f / suma;
        float invb = 1.f / sumb;
        {
            float2 r0 = unpk(oa2[0]), r1 = unpk(oa2[1]), r2 = unpk(oa2[2]), r3 = unpk(oa2[3]);
            int ir = i0 >> 3, jc = i0 & 7;
            size_t pix = ((size_t)(b * 256 + hb * 8 + ir) * 256) + (wb * 8 + jc);
            float4* op = (float4*)(g_x1 + pix * 32 + hq * 8);
            op[0] = make_float4(r0.x * inva, r0.y * inva, r1.x * inva, r1.y * inva);
            op[1] = make_float4(r2.x * inva, r2.y * inva, r3.x * inva, r3.y * inva);
        }
        {
            float2 r0 = unpk(ob2[0]), r1 = unpk(ob2[1]), r2 = unpk(ob2[2]), r3 = unpk(ob2[3]);
            int ir = i1 >> 3, jc = i1 & 7;
            size_t pix = ((size_t)(b * 256 + hb * 8 + ir) * 256) + (wb * 8 + jc);
            float4* op = (float4*)(g_x1 + pix * 32 + hq * 8);
            op[0] = make_float4(r0.x * invb, r0.y * invb, r1.x * invb, r1.y * invb);
            op[1] = make_float4(r2.x * invb, r2.y * invb, r3.x * invb, r3.y * invb);
        }
    }
}

// ---------------- forward row rFFT, 2 real channels per complex warp-FFT --------
__global__ __launch_bounds__(256, 4) void rowfft_kernel(const float* __restrict__ x)
{
    __shared__ float2 sbuf[8 * 256];
    u64* sb = (u64*)sbuf;
    int t  = threadIdx.x;
    int lane = t & 31, w = t >> 5;
    int bx = blockIdx.x;
    int b   = bx >> 9;
    int row = (bx >> 1) & 255;
    int g   = bx & 1;
    u64 neg1 = pack2(-1.f, -1.f);

    const float* xp = x + ((size_t)(b * 256 + row) * 256) * 64 + 32 + g * 16;
    #pragma unroll
    for (int e = 0; e < 8; e++) {
        int l = t + e * 256;
        int n = l >> 3;
        int f = l & 7;
        sb[f * 256 + zin(n, f)] = *(const u64*)(xp + (size_t)n * 64 + 2 * f);
    }
    __syncthreads();

    u64 v[8];
    #pragma unroll
    for (int m2 = 0; m2 < 8; m2++) v[m2] = sb[w * 256 + zin(lane + 32 * m2, w)];
    warp_fft256_fwd(v, lane, neg1);

    int p = rev5(lane);
    const int Q[8] = {0, 4, 2, 6, 1, 5, 3, 7};
    #pragma unroll
    for (int r = 0; r < 8; r++) sb[w * 256 + zq(Q[r], p)] = v[r];
    __syncthreads();

    int img0 = b * 32 + g * 16;
    if (t < 129) {
        int m = (256 - t) & 255;
        int pt = zpos(t), pm = zpos(m);
        #pragma unroll
        for (int f = 0; f < 8; f++) {
            float2 zk = sbuf[f * 256 + pt];
            float2 zm = sbuf[f * 256 + pm];
            float2 A  = make_float2(0.5f * (zk.x + zm.x), 0.5f * (zk.y - zm.y));
            float2 Bv = make_float2(0.5f * (zk.y + zm.y), 0.5f * (zm.x - zk.x));
            size_t o = ((size_t)(img0 + 2 * f) * 256 + row) * 129 + t;
            g_spec[o] = A;
            g_spec[o + (size_t)256 * 129] = Bv;
        }
    }
}

// ---------------- column FFT + amp/phase transform + column IFFT ---------------
__global__ __launch_bounds__(256, 4) void coltrans_kernel(
    const float* __restrict__ amp_w, const float* __restrict__ amp_b,
    const float* __restrict__ pha_w, const float* __restrict__ pha_b)
{
    __shared__ float2 sbuf[8 * 256];
    u64* sb = (u64*)sbuf;
    int t   = threadIdx.x;
    int lane = t & 31, w = t >> 5;
    int img = blockIdx.y;
    int k0  = blockIdx.x * 8;
    int ch  = img & 31;
    u64 neg1 = pack2(-1.f, -1.f);

    float aw = amp_w[ch], ab = amp_b[ch], pw = pha_w[ch], pb = pha_b[ch];

    size_t base = (size_t)img * 256 * 129;
    #pragma unroll
    for (int e = 0; e < 8; e++) {
        int l = t + e * 256;
        int row = l >> 3;
        int kk  = l & 7;
        int k   = k0 + kk;
        float2 vv = make_float2(0.f, 0.f);
        if (k < 129) vv = g_spec[base + (size_t)row * 129 + k];
        sbuf[kk * 256 + zin(row, kk)] = vv;
    }
    __syncthreads();

    u64 v[8];
    #pragma unroll
    for (int m2 = 0; m2 < 8; m2++) v[m2] = sb[w * 256 + zin(lane + 32 * m2, w)];
    warp_fft256_fwd(v, lane, neg1);

    #pragma unroll
    for (int m2 = 0; m2 < 8; m2++) {
        float2 vv = unpk(v[m2]);
        float amp = sqrtf(vv.x * vv.x + vv.y * vv.y);
        float pha = atan2f(vv.y, vv.x);
        float af = amp * aw + ab;
        float pf = pha * pw + pb;
        float sn, cs; __sincosf(pf, &sn, &cs);
        v[m2] = pack2(af * cs + 2e-8f, af * sn + 1e-8f);
    }

    warp_fft256_inv(v, lane, neg1);
    #pragma unroll
    for (int m2 = 0; m2 < 8; m2++) sb[w * 256 + zin(lane + 32 * m2, w)] = v[m2];
    __syncthreads();

    #pragma unroll
    for (int e = 0; e < 8; e++) {
        int l = t + e * 256;
        int row = l >> 3;
        int kk  = l & 7;
        int k   = k0 + kk;
        if (k < 129) g_spec[base + (size_t)row * 129 + k] = sbuf[kk * 256 + zin(row, kk)];
    }
}

// ---------------- inverse row irFFT + abs, 2 image planes per warp-FFT ----------
__global__ __launch_bounds__(256, 4) void rowifft_kernel()
{
    __shared__ float2 sbuf[8 * 256];
    u64* sb = (u64*)sbuf;
    int t  = threadIdx.x;
    int lane = t & 31, w = t >> 5;
    int bx = blockIdx.x;
    int pr   = bx >> 5;
    int row0 = (bx & 31) * 8;
    int imgA = 2 * pr;
    u64 neg1 = pack2(-1.f, -1.f);

    size_t baseA = ((size_t)imgA * 256 + row0) * 129;
    size_t baseB = baseA + (size_t)256 * 129;
    if (t < 129) {
        bool edge = (t == 0) || (t == 128);
        int pt = zpos(t), pm = zpos((256 - t) & 255);
        #pragma unroll
        for (int f = 0; f < 8; f++) {
            float2 A  = g_spec[baseA + (size_t)f * 129 + t];
            float2 Bv = g_spec[baseB + (size_t)f * 129 + t];
            if (edge) { A.y = 0.f; Bv.y = 0.f; }   // irfft discards Im at DC/Nyquist
            sbuf[f * 256 + pt] = make_float2(A.x - Bv.y, A.y + Bv.x);
            if (t >= 1 && t < 128)
                sbuf[f * 256 + pm] = make_float2(A.x + Bv.y, Bv.x - A.y);
        }
    }
    __syncthreads();

    u64 v[8];
    int p = rev5(lane);
    const int Q[8] = {0, 4, 2, 6, 1, 5, 3, 7};
    #pragma unroll
    for (int r = 0; r < 8; r++) v[r] = sb[w * 256 + zq(Q[r], p)];
    warp_fft256_inv(v, lane, neg1);

    size_t oA = ((size_t)imgA * 256 + row0 + w) * 256;
    #pragma unroll
    for (int m2 = 0; m2 < 8; m2++) {
        int n = lane + 32 * m2;
        float2 f = unpk(v[m2]);
        g_x2[oA + n]         = fabsf(f.x * (1.f / 65536.f));
        g_x2[oA + 65536 + n] = fabsf(f.y * (1.f / 65536.f));
    }
}

// ---------------- projection (unchanged, working) ----------------
__global__ __launch_bounds__(64) void proj_kernel(
    const float* __restrict__ pw, const float* __restrict__ pbias,
    float* __restrict__ out)
{
    __shared__ float WsT[64][68];
    __shared__ float x1s[32][68];
    __shared__ float x2s[32][68];
    int t  = threadIdx.x;
    int p0 = blockIdx.x * 64;
    int b    = p0 >> 16;
    int rem0 = p0 & 65535;

    #pragma unroll
    for (int e = 0; e < 64; e++) WsT[t][e] = pw[e * 64 + t];
    #pragma unroll
    for (int e = 0; e < 32; e++) {
        int l = e * 64 + t;
        x1s[l & 31][l >> 5] = g_x1[(size_t)p0 * 32 + l];
    }
    {
        size_t xb = (size_t)b * 2097152 + rem0;
        #pragma unroll
        for (int e = 0; e < 32; e++)
            x2s[e][t] = g_x2[xb + (size_t)e * 65536 + t];
    }
    __syncthreads();

    int pg    = t >> 2;
    int dbase = (t & 3) << 4;
    u64 acc[4][8];
    #pragma unroll
    for (int k = 0; k < 8; k++) {
        u64 bp = *(const u64*)&pbias[dbase + 2 * k];
        #pragma unroll
        for (int p = 0; p < 4; p++) acc[p][k] = bp;
    }

    #pragma unroll
    for (int c = 0; c < 32; c++) {
        float4 a  = *(const float4*)&x1s[c][pg * 4];
        float4 b2 = *(const float4*)&x2s[c][pg * 4];
        u64 ax[4] = {pack2(a.x, a.x),   pack2(a.y, a.y),   pack2(a.z, a.z),   pack2(a.w, a.w)};
        u64 bx[4] = {pack2(b2.x, b2.x), pack2(b2.y, b2.y), pack2(b2.z, b2.z), pack2(b2.w, b2.w)};
        ulonglong2 wA0 = *(const ulonglong2*)&WsT[c][dbase];
        ulonglong2 wA1 = *(const ulonglong2*)&WsT[c][dbase + 4];
        ulonglong2 wA2 = *(const ulonglong2*)&WsT[c][dbase + 8];
        ulonglong2 wA3 = *(const ulonglong2*)&WsT[c][dbase + 12];
        ulonglong2 wB0 = *(const ulonglong2*)&WsT[32 + c][dbase];
        ulonglong2 wB1 = *(const ulonglong2*)&WsT[32 + c][dbase + 4];
        ulonglong2 wB2 = *(const ulonglong2*)&WsT[32 + c][dbase + 8];
        ulonglong2 wB3 = *(const ulonglong2*)&WsT[32 + c][dbase + 12];
        u64 w1[8] = {wA0.x, wA0.y, wA1.x, wA1.y, wA2.x, wA2.y, wA3.x, wA3.y};
        u64 w2[8] = {wB0.x, wB0.y, wB1.x, wB1.y, wB2.x, wB2.y, wB3.x, wB3.y};
        #pragma unroll
        for (int k = 0; k < 8; k++) {
            #pragma unroll
            for (int p = 0; p < 4; p++) {
                acc[p][k] = fma2(ax[p], w1[k], acc[p][k]);
                acc[p][k] = fma2(bx[p], w2[k], acc[p][k]);
            }
        }
    }

    #pragma unroll
    for (int p = 0; p < 4; p++) {
        float* o = out + (size_t)(p0 + pg * 4 + p) * 64 + dbase;
        #pragma unroll
        for (int k = 0; k < 4; k++) {
            float2 lo = unpk(acc[p][2 * k]);
            float2 hi = unpk(acc[p][2 * k + 1]);
            *(float4*)&o[4 * k] = make_float4(lo.x, lo.y, hi.x, hi.y);
        }
    }
}

// ---------------- launch (attn kept at profiled slot #3) ----------------
extern "C" void kernel_launch(void* const* d_in, const int* in_sizes, int n_in,
                              void* d_out, int out_size)
{
    const float* x      = (const float*)d_in[0];
    const float* w_qkv  = (const float*)d_in[1];
    const float* b_qkv  = (const float*)d_in[2];
    const float* pos    = (const float*)d_in[3];
    const float* amp_w  = (const float*)d_in[4];
    const float* amp_b  = (const float*)d_in[5];
    const float* pha_w  = (const float*)d_in[6];
    const float* pha_b  = (const float*)d_in[7];
    const float* proj_w = (const float*)d_in[8];
    const float* proj_b = (const float*)d_in[9];
    float* out = (float*)d_out;

    transpose_pos_kernel<<<64, 256>>>(pos);
    rowfft_kernel<<<4096, 256>>>(x);
    coltrans_kernel<<<dim3(17, 256), 256>>>(amp_w, amp_b, pha_w, pha_b);
    attn_kernel<<<8192, 128>>>(x, w_qkv, b_qkv);
    rowifft_kernel<<<4096, 256>>>();
    proj_kernel<<<8192, 64>>>(proj_w, proj_b, out);
}